// round 10
// baseline (speedup 1.0000x reference)
#include <cuda_runtime.h>
#include <cuda_bf16.h>
#include <cstdint>

#define Bq 16
#define Tq 2048
#define Dq 256
#define Nq 512

#define Q_ELEMS (Bq*Tq*Dq)          /* 8388608 */
#define DIFF_OFF Q_ELEMS
#define IND_OFF  (Q_ELEMS + 1)
#define GATHER_BLOCKS (Bq*Tq/16)    /* 2048 */
#define EPS_SEL 1.0f
#define ASTRIDE 144                  /* smem row stride bytes (128 data + 16 pad) */

// ---------------- scratch (no allocations allowed) ----------------
__device__ float g_cb[Bq*Nq*Dq];                       // e codebook [b][n][d]
__device__ float g_see[Bq*Nq];                         // sum(e^2), XLA-tree order
__device__ float g_sxx[Bq*Tq];                         // sum(x^2), XLA-tree order
__device__ __align__(16) __nv_bfloat16 g_xb[Bq*Tq*Dq]; // x bf16
__device__ __align__(16) __nv_bfloat16 g_eb[Bq*Nq*Dq]; // e bf16
__device__ float g_dot[(size_t)Bq*Tq*Nq];              // approx dots, 67 MB
__device__ unsigned g_bestn[Bq*Tq];
__device__ double g_diff_partial[GATHER_BLOCKS];

// ---------------- helpers ----------------
__device__ __forceinline__ unsigned long long make_key(float s, int n) {
    unsigned u = __float_as_uint(s);
    u = (u & 0x80000000u) ? ~u : (u | 0x80000000u);
    return ((unsigned long long)u << 32) | (unsigned long long)(0xFFFFFFFFu - (unsigned)n);
}
__device__ __forceinline__ unsigned long long fma2(unsigned long long a,
                                                   unsigned long long x,
                                                   unsigned long long e) {
    asm("fma.rn.f32x2 %0, %1, %2, %0;" : "+l"(a) : "l"(x), "l"(e));
    return a;
}
__device__ __forceinline__ unsigned long long dup2(float v) {
    unsigned long long r; asm("mov.b64 %0, {%1, %1};" : "=l"(r) : "f"(v)); return r;
}
__device__ __forceinline__ unsigned long long pack2(float lo, float hi) {
    unsigned long long r; asm("mov.b64 %0, {%1, %2};" : "=l"(r) : "f"(lo), "f"(hi)); return r;
}
__device__ __forceinline__ void unpack2(unsigned long long v, float& lo, float& hi) {
    asm("mov.b64 {%0, %1}, %2;" : "=f"(lo), "=f"(hi) : "l"(v));
}
__device__ __forceinline__ float warp_tree_sum(float p) {
#pragma unroll
    for (int off = 16; off > 0; off >>= 1)
        p = __fadd_rn(p, __shfl_down_sync(0xffffffffu, p, off));
    return p;
}
__device__ __forceinline__ uint32_t smem_u32(const void* p) {
    uint32_t a;
    asm("{ .reg .u64 t; cvta.to.shared.u64 t, %1; cvt.u32.u64 %0, t; }" : "=r"(a) : "l"(p));
    return a;
}
__device__ __forceinline__ void ldsm_x4(uint32_t r[4], uint32_t addr) {
    asm volatile("ldmatrix.sync.aligned.m8n8.x4.shared.b16 {%0,%1,%2,%3}, [%4];"
        : "=r"(r[0]), "=r"(r[1]), "=r"(r[2]), "=r"(r[3]) : "r"(addr));
}
__device__ __forceinline__ void mma16816(float c[4], const uint32_t a[4],
                                         uint32_t b0, uint32_t b1) {
    asm volatile("mma.sync.aligned.m16n8k16.row.col.f32.bf16.bf16.f32 "
        "{%0,%1,%2,%3}, {%4,%5,%6,%7}, {%8,%9}, {%0,%1,%2,%3};"
        : "+f"(c[0]), "+f"(c[1]), "+f"(c[2]), "+f"(c[3])
        : "r"(a[0]), "r"(a[1]), "r"(a[2]), "r"(a[3]), "r"(b0), "r"(b1));
}

// ---------------- kernel 0: sxx (XLA order) + x bf16 --------------
__global__ __launch_bounds__(256) void k_prep(const float* __restrict__ x) {
    int tid = threadIdx.x, lane = tid & 31, wid = tid >> 5;
    int token = blockIdx.x * 8 + wid;
    const float* xt = x + (size_t)token * Dq;
    float p = 0.f;
#pragma unroll
    for (int j = 0; j < 8; j++) {
        float c = xt[lane + 32*j];
        p = __fadd_rn(p, __fmul_rn(c, c));
        g_xb[(size_t)token * Dq + lane + 32*j] = __float2bfloat16(c);
    }
    p = warp_tree_sum(p);
    if (lane == 0) g_sxx[token] = p;
}

// ---------------- kernel 1: codebook build (+ e bf16) -------------
__global__ __launch_bounds__(128) void k_codebook(const float* __restrict__ emb,
                                                  const float* __restrict__ spk) {
    __shared__ float As[256*33];
    __shared__ unsigned long long Ms2[8*32];
    __shared__ float normS[16];

    int tid = threadIdx.x;
    int lane = tid & 31, wid = tid >> 5;
    int n = blockIdx.x;
    const float* embn = emb + (size_t)n * (Dq*Dq);
    const float* mul  = spk + 2*Bq*Dq;
    const float* addv = spk + 1*Bq*Dq;

    unsigned long long accp[2][8];
#pragma unroll
    for (int r = 0; r < 2; r++)
#pragma unroll
        for (int p = 0; p < 8; p++) accp[r][p] = 0ull;

    for (int kc = 0; kc < 256; kc += 32) {
        __syncthreads();
        for (int i = tid; i < 256; i += 128) {
            int p = i >> 5, j = i & 31;
            Ms2[i] = pack2(mul[(2*p)*256 + kc + j], mul[(2*p+1)*256 + kc + j]);
        }
        for (int f = tid; f < 2048; f += 128) {
            int d = f >> 3, jg = f & 7;
            float4 v = *(const float4*)(embn + (size_t)d*256 + kc + jg*4);
            int base = d*33 + jg*4;
            As[base+0] = v.x; As[base+1] = v.y; As[base+2] = v.z; As[base+3] = v.w;
        }
        __syncthreads();

        const float* a0 = As + tid*33;
        const float* a1 = As + (tid+128)*33;
#pragma unroll 4
        for (int j = 0; j < 32; j++) {
            unsigned long long xv0 = dup2(a0[j]);
            unsigned long long xv1 = dup2(a1[j]);
#pragma unroll
            for (int p = 0; p < 8; p++) {
                unsigned long long m = Ms2[p*32 + j];
                accp[0][p] = fma2(accp[0][p], xv0, m);
                accp[1][p] = fma2(accp[1][p], xv1, m);
            }
        }
    }

    float acc[2][16];
#pragma unroll
    for (int r = 0; r < 2; r++)
#pragma unroll
        for (int p = 0; p < 8; p++)
            unpack2(accp[r][p], acc[r][2*p], acc[r][2*p+1]);

    __syncthreads();
#pragma unroll
    for (int r = 0; r < 2; r++)
#pragma unroll
        for (int b = 0; b < 16; b++) As[b*258 + tid + r*128] = acc[r][b];
    __syncthreads();

#pragma unroll
    for (int bb = 0; bb < 4; bb++) {
        int b = wid*4 + bb;
        const float* row = As + b*258;
        float p = 0.f;
#pragma unroll
        for (int j = 0; j < 8; j++) {
            float c = row[lane + 32*j];
            p = __fadd_rn(p, __fmul_rn(c, c));
        }
        p = warp_tree_sum(p);
        if (lane == 0) normS[b] = __fsqrt_rn(p);
    }
    __syncthreads();

#pragma unroll
    for (int r = 0; r < 2; r++) {
        int d = tid + r*128;
#pragma unroll
        for (int b = 0; b < 16; b++) {
            float ef = __fadd_rn(__fdiv_rn(acc[r][b], normS[b]), addv[b*256 + d]);
            size_t o = ((size_t)(b*Nq + n))*Dq + d;
            g_cb[o] = ef;
            As[b*258 + d] = ef;
            g_eb[o] = __float2bfloat16(ef);
        }
    }
    __syncthreads();

#pragma unroll
    for (int bb = 0; bb < 4; bb++) {
        int b = wid*4 + bb;
        const float* row = As + b*258;
        float p = 0.f;
#pragma unroll
        for (int j = 0; j < 8; j++) {
            float c = row[lane + 32*j];
            p = __fadd_rn(p, __fmul_rn(c, c));
        }
        p = warp_tree_sum(p);
        if (lane == 0) g_see[b*Nq + n] = p;
    }
}

// ---------------- kernel 2: HMMA bf16 single-segment dot GEMM -------------
// tile 128t x 128n, 8 warps (2x4), per-warp 64t x 32n via 4x4 m16n8k16.
__global__ __launch_bounds__(256, 2) void k_scores_mma() {
    __shared__ __align__(16) unsigned char sA[128*ASTRIDE];
    __shared__ __align__(16) unsigned char sB[128*ASTRIDE];

    int tid = threadIdx.x, wid = tid >> 5, lane = tid & 31;
    int tile = blockIdx.x;
    int b = tile >> 6, rem = tile & 63;
    int t0 = (rem >> 2) * 128, n0 = (rem & 3) * 128;
    int wy = wid >> 2, wx = wid & 3;

    float acc[4][4][4];
#pragma unroll
    for (int i = 0; i < 4; i++)
#pragma unroll
        for (int j = 0; j < 4; j++)
#pragma unroll
            for (int c = 0; c < 4; c++) acc[i][j][c] = 0.f;

    int lrow = tid >> 1, lhalf = tid & 1;   // gmem->smem: 64B per thread per operand

    uint32_t aBase = smem_u32(sA), bBase = smem_u32(sB);
    uint32_t aAddr0 = aBase + (uint32_t)(wy*64 + (lane & 15)) * ASTRIDE + ((lane >> 4) * 16);
    uint32_t bAddr0 = bBase + (uint32_t)(wx*32 + ((lane >> 4) << 3) + (lane & 7)) * ASTRIDE
                            + (((lane >> 3) & 1) * 16);

    const __nv_bfloat16* gX = g_xb + ((size_t)(b*Tq + t0)) * Dq;
    const __nv_bfloat16* gE = g_eb + ((size_t)(b*Nq + n0)) * Dq;

    uint4 pa[4], pb[4];
    {
        const uint4* srcA = (const uint4*)(gX + (size_t)lrow*Dq + lhalf*32);
        const uint4* srcB = (const uint4*)(gE + (size_t)lrow*Dq + lhalf*32);
#pragma unroll
        for (int q = 0; q < 4; q++) { pa[q] = srcA[q]; pb[q] = srcB[q]; }
    }

    for (int c = 0; c < 4; c++) {           // 4 k-chunks of 64
        __syncthreads();                    // previous chunk's MMAs done reading smem
        {
            uint4* dstA = (uint4*)(sA + lrow*ASTRIDE + lhalf*64);
            uint4* dstB = (uint4*)(sB + lrow*ASTRIDE + lhalf*64);
#pragma unroll
            for (int q = 0; q < 4; q++) { dstA[q] = pa[q]; dstB[q] = pb[q]; }
        }
        __syncthreads();
        if (c < 3) {
            int kc = (c + 1) * 64;
            const uint4* srcA = (const uint4*)(gX + (size_t)lrow*Dq + kc + lhalf*32);
            const uint4* srcB = (const uint4*)(gE + (size_t)lrow*Dq + kc + lhalf*32);
#pragma unroll
            for (int q = 0; q < 4; q++) { pa[q] = srcA[q]; pb[q] = srcB[q]; }
        }
#pragma unroll
        for (int s = 0; s < 4; s++) {       // 4 k16 steps per chunk
            uint32_t bfr[2][4];
#pragma unroll
            for (int p = 0; p < 2; p++)
                ldsm_x4(bfr[p], bAddr0 + (uint32_t)(p*16)*ASTRIDE + s*32);
#pragma unroll
            for (int mt = 0; mt < 4; mt++) {
                uint32_t afr[4];
                ldsm_x4(afr, aAddr0 + (uint32_t)(mt*16)*ASTRIDE + s*32);
#pragma unroll
                for (int nt = 0; nt < 4; nt++) {
                    int p = nt >> 1, q = nt & 1;
                    mma16816(acc[mt][nt], afr, bfr[p][2*q], bfr[p][2*q + 1]);
                }
            }
        }
    }

    // epilogue: store raw dots
    int gid = lane >> 2, tid4 = lane & 3;
#pragma unroll
    for (int mt = 0; mt < 4; mt++) {
        int t = t0 + wy*64 + mt*16 + gid;
        float* d0 = g_dot + ((size_t)(b*Tq) + t) * Nq;
        float* d1 = g_dot + ((size_t)(b*Tq) + t + 8) * Nq;
#pragma unroll
        for (int nt = 0; nt < 4; nt++) {
            int n = n0 + wx*32 + nt*8 + tid4*2;
            *(float2*)(d0 + n) = make_float2(acc[mt][nt][0], acc[mt][nt][1]);
            *(float2*)(d1 + n) = make_float2(acc[mt][nt][2], acc[mt][nt][3]);
        }
    }
}

// ---------------- kernel 3: select — approx min + exact rescore -----------
__global__ __launch_bounds__(256) void k_select(const float* __restrict__ x,
                                                float* __restrict__ out) {
    int tid = threadIdx.x, lane = tid & 31, wid = tid >> 5;
    int token = blockIdx.x * 8 + wid;
    int b = token >> 11;
    float sxx = g_sxx[token];
    const float4* d4 = (const float4*)(g_dot + (size_t)token * Nq);
    const float4* s4 = (const float4*)(g_see + b * Nq);

    float dloc[16];
    float dmin = 3.4e38f;
#pragma unroll
    for (int j = 0; j < 4; j++) {
        float4 dv = d4[lane + 32*j];
        float4 sv = s4[lane + 32*j];
        float q0 = __fadd_rn(__fsub_rn(sxx, __fmul_rn(2.0f, dv.x)), sv.x);
        float q1 = __fadd_rn(__fsub_rn(sxx, __fmul_rn(2.0f, dv.y)), sv.y);
        float q2 = __fadd_rn(__fsub_rn(sxx, __fmul_rn(2.0f, dv.z)), sv.z);
        float q3 = __fadd_rn(__fsub_rn(sxx, __fmul_rn(2.0f, dv.w)), sv.w);
        dloc[4*j+0] = q0; dloc[4*j+1] = q1; dloc[4*j+2] = q2; dloc[4*j+3] = q3;
        dmin = fminf(dmin, fminf(fminf(q0, q1), fminf(q2, q3)));
    }
#pragma unroll
    for (int off = 16; off > 0; off >>= 1)
        dmin = fminf(dmin, __shfl_xor_sync(0xffffffffu, dmin, off));

    float thr = dmin + EPS_SEL;
    int cnt = 0;
#pragma unroll
    for (int j = 0; j < 16; j++) cnt += (dloc[j] <= thr);
    int total = cnt;
#pragma unroll
    for (int off = 16; off > 0; off >>= 1)
        total += __shfl_xor_sync(0xffffffffu, total, off);

    unsigned nstar;
    if (total == 1) {
        unsigned nm = 0xFFFFFFFFu;
#pragma unroll
        for (int j = 0; j < 16; j++)
            if (dloc[j] <= thr) nm = (unsigned)(4*(lane + 32*(j >> 2)) + (j & 3));
#pragma unroll
        for (int off = 16; off > 0; off >>= 1)
            nm = min(nm, __shfl_xor_sync(0xffffffffu, nm, off));
        nstar = nm;
    } else {
        // exact rescore of candidates: sequential fp32 fmaf chain (ref-exact)
        unsigned long long bk = 0ull;
        const float* xr = x + (size_t)token * Dq;
#pragma unroll
        for (int j = 0; j < 16; j++) {
            if (dloc[j] <= thr) {
                int n = 4*(lane + 32*(j >> 2)) + (j & 3);
                const float* er = g_cb + ((size_t)(b*Nq + n))*Dq;
                float acc = 0.f;
                for (int k = 0; k < 256; k++)
                    acc = __fmaf_rn(xr[k], er[k], acc);
                float dist = __fadd_rn(__fsub_rn(sxx, __fmul_rn(2.0f, acc)), g_see[b*Nq + n]);
                unsigned long long key = make_key(-dist, n);
                if (key > bk) bk = key;
            }
        }
#pragma unroll
        for (int off = 16; off > 0; off >>= 1) {
            unsigned long long o = __shfl_xor_sync(0xffffffffu, bk, off);
            if (o > bk) bk = o;
        }
        nstar = 0xFFFFFFFFu - (unsigned)bk;
    }
    if (lane == 0) {
        g_bestn[token] = nstar;
        out[IND_OFF + token] = (float)nstar;
    }
}

// ---------------- kernel 4: gather + outputs + diff partials --------------
__global__ __launch_bounds__(256) void k_gather(const float* __restrict__ x,
                                                float* __restrict__ out) {
    __shared__ unsigned ns[16];
    __shared__ double s_red[8];
    int tid = threadIdx.x, lane = tid & 31, wid = tid >> 5;
    int tok0 = blockIdx.x * 16;
    int b = tok0 >> 11;

    if (tid < 16) ns[tid] = g_bestn[tok0 + tid];
    __syncthreads();

    const float* cbb = g_cb + (size_t)b * Nq * Dq;
    const float4* x4 = (const float4*)(x + (size_t)tok0 * Dq);
    float4* o4 = (float4*)(out + (size_t)tok0 * Dq);

    float s32 = 0.f;
    double s = 0.0;
#pragma unroll
    for (int i = 0; i < 4; i++) {
        int f = tid + i*256;
        int tl = f >> 6;
        int dd = (f & 63);
        float4 q = ((const float4*)(cbb + (size_t)ns[tl]*Dq))[dd];
        float4 xv = x4[f];
        float dx = __fsub_rn(q.x, xv.x), dy = __fsub_rn(q.y, xv.y);
        float dz = __fsub_rn(q.z, xv.z), dw = __fsub_rn(q.w, xv.w);
        float4 r;
        r.x = __fmul_rn(__fadd_rn(q.x, __fadd_rn(xv.x, dx)), 0.5f);
        r.y = __fmul_rn(__fadd_rn(q.y, __fadd_rn(xv.y, dy)), 0.5f);
        r.z = __fmul_rn(__fadd_rn(q.z, __fadd_rn(xv.z, dz)), 0.5f);
        r.w = __fmul_rn(__fadd_rn(q.w, __fadd_rn(xv.w, dw)), 0.5f);
        o4[f] = r;
        s32 = fmaf(dx, dx, s32); s32 = fmaf(dy, dy, s32);
        s32 = fmaf(dz, dz, s32); s32 = fmaf(dw, dw, s32);
        if (i == 1) { s += (double)s32; s32 = 0.f; }
    }
    s += (double)s32;

#pragma unroll
    for (int off = 16; off > 0; off >>= 1) s += __shfl_down_sync(0xffffffffu, s, off);
    if (lane == 0) s_red[wid] = s;
    __syncthreads();
    if (tid == 0) {
        double t = 0.0;
        for (int i = 0; i < 8; i++) t += s_red[i];
        g_diff_partial[blockIdx.x] = t;
    }
}

// ---------------- kernel 5: deterministic final diff reduce ---------------
__global__ __launch_bounds__(256) void k_diff(float* __restrict__ out) {
    __shared__ double sr[256];
    int tid = threadIdx.x;
    double s = 0.0;
    for (int i = tid; i < GATHER_BLOCKS; i += 256) s += g_diff_partial[i];
    sr[tid] = s;
    __syncthreads();
    for (int off = 128; off > 0; off >>= 1) {
        if (tid < off) sr[tid] += sr[tid + off];
        __syncthreads();
    }
    if (tid == 0) out[DIFF_OFF] = (float)(sr[0] / (double)Q_ELEMS);
}

// ---------------- launch ----------------
extern "C" void kernel_launch(void* const* d_in, const int* in_sizes, int n_in,
                              void* d_out, int out_size) {
    const float* inp = (const float*)d_in[0];   // (16,2048,256)
    const float* spk = (const float*)d_in[1];   // (3,16,256)
    const float* emb = (const float*)d_in[2];   // (512,256,256)
    float* out = (float*)d_out;                 // [quantize | diff | embed_ind]

    k_prep<<<Bq*Tq/8, 256>>>(inp);
    k_codebook<<<512, 128>>>(emb, spk);
    k_scores_mma<<<1024, 256>>>();
    k_select<<<Bq*Tq/8, 256>>>(inp, out);
    k_gather<<<GATHER_BLOCKS, 256>>>(inp, out);
    k_diff<<<1, 256>>>(out);
}

// round 11
// speedup vs baseline: 1.4604x; 1.4604x over previous
#include <cuda_runtime.h>
#include <cuda_bf16.h>
#include <cstdint>

#define Bq 16
#define Tq 2048
#define Dq 256
#define Nq 512

#define Q_ELEMS (Bq*Tq*Dq)          /* 8388608 */
#define DIFF_OFF Q_ELEMS
#define IND_OFF  (Q_ELEMS + 1)
#define GATHER_BLOCKS (Bq*Tq/16)    /* 2048 */
#define EPS_SEL 0.25f
#define ASTRIDE 144                  /* smem row stride bytes (128 data + 16 pad) */

// ---------------- scratch (no allocations allowed) ----------------
__device__ float g_cb[Bq*Nq*Dq];                       // e codebook [b][n][d]
__device__ float g_see[Bq*Nq];                         // sum(e^2), XLA-tree order
__device__ float g_sxx[Bq*Tq];                         // sum(x^2), XLA-tree order
__device__ __align__(16) __nv_bfloat16 g_xb[Bq*Tq*Dq]; // x bf16
__device__ __align__(16) __nv_bfloat16 g_eb[Bq*Nq*Dq]; // e bf16
__device__ float g_dot[(size_t)Bq*Tq*Nq];              // approx dots, 67 MB
__device__ unsigned g_bestn[Bq*Tq];
__device__ double g_diff_partial[GATHER_BLOCKS];

// ---------------- helpers ----------------
__device__ __forceinline__ unsigned long long make_key(float s, int n) {
    unsigned u = __float_as_uint(s);
    u = (u & 0x80000000u) ? ~u : (u | 0x80000000u);
    return ((unsigned long long)u << 32) | (unsigned long long)(0xFFFFFFFFu - (unsigned)n);
}
__device__ __forceinline__ unsigned long long fma2(unsigned long long a,
                                                   unsigned long long x,
                                                   unsigned long long e) {
    asm("fma.rn.f32x2 %0, %1, %2, %0;" : "+l"(a) : "l"(x), "l"(e));
    return a;
}
__device__ __forceinline__ unsigned long long dup2(float v) {
    unsigned long long r; asm("mov.b64 %0, {%1, %1};" : "=l"(r) : "f"(v)); return r;
}
__device__ __forceinline__ unsigned long long pack2(float lo, float hi) {
    unsigned long long r; asm("mov.b64 %0, {%1, %2};" : "=l"(r) : "f"(lo), "f"(hi)); return r;
}
__device__ __forceinline__ void unpack2(unsigned long long v, float& lo, float& hi) {
    asm("mov.b64 {%0, %1}, %2;" : "=f"(lo), "=f"(hi) : "l"(v));
}
__device__ __forceinline__ float warp_tree_sum(float p) {
#pragma unroll
    for (int off = 16; off > 0; off >>= 1)
        p = __fadd_rn(p, __shfl_down_sync(0xffffffffu, p, off));
    return p;
}
__device__ __forceinline__ uint32_t smem_u32(const void* p) {
    uint32_t a;
    asm("{ .reg .u64 t; cvta.to.shared.u64 t, %1; cvt.u32.u64 %0, t; }" : "=r"(a) : "l"(p));
    return a;
}
__device__ __forceinline__ void ldsm_x4(uint32_t r[4], uint32_t addr) {
    asm volatile("ldmatrix.sync.aligned.m8n8.x4.shared.b16 {%0,%1,%2,%3}, [%4];"
        : "=r"(r[0]), "=r"(r[1]), "=r"(r[2]), "=r"(r[3]) : "r"(addr));
}
__device__ __forceinline__ void mma16816(float c[4], const uint32_t a[4],
                                         uint32_t b0, uint32_t b1) {
    asm volatile("mma.sync.aligned.m16n8k16.row.col.f32.bf16.bf16.f32 "
        "{%0,%1,%2,%3}, {%4,%5,%6,%7}, {%8,%9}, {%0,%1,%2,%3};"
        : "+f"(c[0]), "+f"(c[1]), "+f"(c[2]), "+f"(c[3])
        : "r"(a[0]), "r"(a[1]), "r"(a[2]), "r"(a[3]), "r"(b0), "r"(b1));
}

// ---------------- kernel 0: sxx (XLA order) + x bf16 --------------
__global__ __launch_bounds__(256) void k_prep(const float* __restrict__ x) {
    int tid = threadIdx.x, lane = tid & 31, wid = tid >> 5;
    int token = blockIdx.x * 8 + wid;
    const float* xt = x + (size_t)token * Dq;
    float p = 0.f;
#pragma unroll
    for (int j = 0; j < 8; j++) {
        float c = xt[lane + 32*j];
        p = __fadd_rn(p, __fmul_rn(c, c));
        g_xb[(size_t)token * Dq + lane + 32*j] = __float2bfloat16(c);
    }
    p = warp_tree_sum(p);
    if (lane == 0) g_sxx[token] = p;
}

// ---------------- kernel 1: codebook build (+ e bf16) -------------
__global__ __launch_bounds__(128) void k_codebook(const float* __restrict__ emb,
                                                  const float* __restrict__ spk) {
    __shared__ float As[256*33];
    __shared__ unsigned long long Ms2[8*32];
    __shared__ float normS[16];

    int tid = threadIdx.x;
    int lane = tid & 31, wid = tid >> 5;
    int n = blockIdx.x;
    const float* embn = emb + (size_t)n * (Dq*Dq);
    const float* mul  = spk + 2*Bq*Dq;
    const float* addv = spk + 1*Bq*Dq;

    unsigned long long accp[2][8];
#pragma unroll
    for (int r = 0; r < 2; r++)
#pragma unroll
        for (int p = 0; p < 8; p++) accp[r][p] = 0ull;

    for (int kc = 0; kc < 256; kc += 32) {
        __syncthreads();
        for (int i = tid; i < 256; i += 128) {
            int p = i >> 5, j = i & 31;
            Ms2[i] = pack2(mul[(2*p)*256 + kc + j], mul[(2*p+1)*256 + kc + j]);
        }
        for (int f = tid; f < 2048; f += 128) {
            int d = f >> 3, jg = f & 7;
            float4 v = *(const float4*)(embn + (size_t)d*256 + kc + jg*4);
            int base = d*33 + jg*4;
            As[base+0] = v.x; As[base+1] = v.y; As[base+2] = v.z; As[base+3] = v.w;
        }
        __syncthreads();

        const float* a0 = As + tid*33;
        const float* a1 = As + (tid+128)*33;
#pragma unroll 4
        for (int j = 0; j < 32; j++) {
            unsigned long long xv0 = dup2(a0[j]);
            unsigned long long xv1 = dup2(a1[j]);
#pragma unroll
            for (int p = 0; p < 8; p++) {
                unsigned long long m = Ms2[p*32 + j];
                accp[0][p] = fma2(accp[0][p], xv0, m);
                accp[1][p] = fma2(accp[1][p], xv1, m);
            }
        }
    }

    float acc[2][16];
#pragma unroll
    for (int r = 0; r < 2; r++)
#pragma unroll
        for (int p = 0; p < 8; p++)
            unpack2(accp[r][p], acc[r][2*p], acc[r][2*p+1]);

    __syncthreads();
#pragma unroll
    for (int r = 0; r < 2; r++)
#pragma unroll
        for (int b = 0; b < 16; b++) As[b*258 + tid + r*128] = acc[r][b];
    __syncthreads();

#pragma unroll
    for (int bb = 0; bb < 4; bb++) {
        int b = wid*4 + bb;
        const float* row = As + b*258;
        float p = 0.f;
#pragma unroll
        for (int j = 0; j < 8; j++) {
            float c = row[lane + 32*j];
            p = __fadd_rn(p, __fmul_rn(c, c));
        }
        p = warp_tree_sum(p);
        if (lane == 0) normS[b] = __fsqrt_rn(p);
    }
    __syncthreads();

#pragma unroll
    for (int r = 0; r < 2; r++) {
        int d = tid + r*128;
#pragma unroll
        for (int b = 0; b < 16; b++) {
            float ef = __fadd_rn(__fdiv_rn(acc[r][b], normS[b]), addv[b*256 + d]);
            size_t o = ((size_t)(b*Nq + n))*Dq + d;
            g_cb[o] = ef;
            As[b*258 + d] = ef;
            g_eb[o] = __float2bfloat16(ef);
        }
    }
    __syncthreads();

#pragma unroll
    for (int bb = 0; bb < 4; bb++) {
        int b = wid*4 + bb;
        const float* row = As + b*258;
        float p = 0.f;
#pragma unroll
        for (int j = 0; j < 8; j++) {
            float c = row[lane + 32*j];
            p = __fadd_rn(p, __fmul_rn(c, c));
        }
        p = warp_tree_sum(p);
        if (lane == 0) g_see[b*Nq + n] = p;
    }
}

// ---------------- kernel 2: HMMA bf16 single-segment dot GEMM -------------
// tile 128t x 128n, 8 warps (2x4), per-warp 64t x 32n via 4x4 m16n8k16.
__global__ __launch_bounds__(256, 2) void k_scores_mma() {
    __shared__ __align__(16) unsigned char sA[128*ASTRIDE];
    __shared__ __align__(16) unsigned char sB[128*ASTRIDE];

    int tid = threadIdx.x, wid = tid >> 5, lane = tid & 31;
    int tile = blockIdx.x;
    int b = tile >> 6, rem = tile & 63;
    int t0 = (rem >> 2) * 128, n0 = (rem & 3) * 128;
    int wy = wid >> 2, wx = wid & 3;

    float acc[4][4][4];
#pragma unroll
    for (int i = 0; i < 4; i++)
#pragma unroll
        for (int j = 0; j < 4; j++)
#pragma unroll
            for (int c = 0; c < 4; c++) acc[i][j][c] = 0.f;

    int lrow = tid >> 1, lhalf = tid & 1;   // gmem->smem: 64B per thread per operand

    uint32_t aBase = smem_u32(sA), bBase = smem_u32(sB);
    uint32_t aAddr0 = aBase + (uint32_t)(wy*64 + (lane & 15)) * ASTRIDE + ((lane >> 4) * 16);
    uint32_t bAddr0 = bBase + (uint32_t)(wx*32 + ((lane >> 4) << 3) + (lane & 7)) * ASTRIDE
                            + (((lane >> 3) & 1) * 16);

    const __nv_bfloat16* gX = g_xb + ((size_t)(b*Tq + t0)) * Dq;
    const __nv_bfloat16* gE = g_eb + ((size_t)(b*Nq + n0)) * Dq;

    uint4 pa[4], pb[4];
    {
        const uint4* srcA = (const uint4*)(gX + (size_t)lrow*Dq + lhalf*32);
        const uint4* srcB = (const uint4*)(gE + (size_t)lrow*Dq + lhalf*32);
#pragma unroll
        for (int q = 0; q < 4; q++) { pa[q] = srcA[q]; pb[q] = srcB[q]; }
    }

    for (int c = 0; c < 4; c++) {           // 4 k-chunks of 64
        __syncthreads();                    // previous chunk's MMAs done reading smem
        {
            uint4* dstA = (uint4*)(sA + lrow*ASTRIDE + lhalf*64);
            uint4* dstB = (uint4*)(sB + lrow*ASTRIDE + lhalf*64);
#pragma unroll
            for (int q = 0; q < 4; q++) { dstA[q] = pa[q]; dstB[q] = pb[q]; }
        }
        __syncthreads();
        if (c < 3) {
            int kc = (c + 1) * 64;
            const uint4* srcA = (const uint4*)(gX + (size_t)lrow*Dq + kc + lhalf*32);
            const uint4* srcB = (const uint4*)(gE + (size_t)lrow*Dq + kc + lhalf*32);
#pragma unroll
            for (int q = 0; q < 4; q++) { pa[q] = srcA[q]; pb[q] = srcB[q]; }
        }
#pragma unroll
        for (int s = 0; s < 4; s++) {       // 4 k16 steps per chunk
            uint32_t bfr[2][4];
#pragma unroll
            for (int p = 0; p < 2; p++)
                ldsm_x4(bfr[p], bAddr0 + (uint32_t)(p*16)*ASTRIDE + s*32);
#pragma unroll
            for (int mt = 0; mt < 4; mt++) {
                uint32_t afr[4];
                ldsm_x4(afr, aAddr0 + (uint32_t)(mt*16)*ASTRIDE + s*32);
#pragma unroll
                for (int nt = 0; nt < 4; nt++) {
                    int p = nt >> 1, q = nt & 1;
                    mma16816(acc[mt][nt], afr, bfr[p][2*q], bfr[p][2*q + 1]);
                }
            }
        }
    }

    // epilogue: store raw dots
    int gid = lane >> 2, tid4 = lane & 3;
#pragma unroll
    for (int mt = 0; mt < 4; mt++) {
        int t = t0 + wy*64 + mt*16 + gid;
        float* d0 = g_dot + ((size_t)(b*Tq) + t) * Nq;
        float* d1 = g_dot + ((size_t)(b*Tq) + t + 8) * Nq;
#pragma unroll
        for (int nt = 0; nt < 4; nt++) {
            int n = n0 + wx*32 + nt*8 + tid4*2;
            *(float2*)(d0 + n) = make_float2(acc[mt][nt][0], acc[mt][nt][1]);
            *(float2*)(d1 + n) = make_float2(acc[mt][nt][2], acc[mt][nt][3]);
        }
    }
}

// ---------------- kernel 3: select — approx min + exact rescore -----------
__global__ __launch_bounds__(256) void k_select(const float* __restrict__ x,
                                                float* __restrict__ out) {
    int tid = threadIdx.x, lane = tid & 31, wid = tid >> 5;
    int token = blockIdx.x * 8 + wid;
    int b = token >> 11;
    float sxx = g_sxx[token];
    const float* dotp = g_dot + (size_t)token * Nq;
    const float* seep = g_see + b * Nq;

    float dloc[16];
    float dmin = 3.4e38f;
#pragma unroll
    for (int j = 0; j < 16; j++) {
        int n = lane + 32*j;
        float dist = __fadd_rn(__fsub_rn(sxx, __fmul_rn(2.0f, dotp[n])), seep[n]);
        dloc[j] = dist;
        dmin = fminf(dmin, dist);
    }
#pragma unroll
    for (int off = 16; off > 0; off >>= 1)
        dmin = fminf(dmin, __shfl_xor_sync(0xffffffffu, dmin, off));

    float thr = dmin + EPS_SEL;
    int cnt = 0;
#pragma unroll
    for (int j = 0; j < 16; j++) cnt += (dloc[j] <= thr);
    int total = cnt;
#pragma unroll
    for (int off = 16; off > 0; off >>= 1)
        total += __shfl_xor_sync(0xffffffffu, total, off);

    unsigned nstar;
    if (total == 1) {
        unsigned nm = 0xFFFFFFFFu;
#pragma unroll
        for (int j = 0; j < 16; j++)
            if (dloc[j] <= thr) nm = (unsigned)(lane + 32*j);
#pragma unroll
        for (int off = 16; off > 0; off >>= 1)
            nm = min(nm, __shfl_xor_sync(0xffffffffu, nm, off));
        nstar = nm;
    } else {
        // exact rescore of candidates: sequential fp32 fmaf chain (ref-exact)
        unsigned long long bk = 0ull;
        const float* xr = x + (size_t)token * Dq;
        for (int j = 0; j < 16; j++) {
            if (dloc[j] <= thr) {
                int n = lane + 32*j;
                const float* er = g_cb + ((size_t)(b*Nq + n))*Dq;
                float acc = 0.f;
                for (int k = 0; k < 256; k++)
                    acc = __fmaf_rn(xr[k], er[k], acc);
                float dist = __fadd_rn(__fsub_rn(sxx, __fmul_rn(2.0f, acc)), seep[n]);
                unsigned long long key = make_key(-dist, n);
                if (key > bk) bk = key;
            }
        }
#pragma unroll
        for (int off = 16; off > 0; off >>= 1) {
            unsigned long long o = __shfl_xor_sync(0xffffffffu, bk, off);
            if (o > bk) bk = o;
        }
        nstar = 0xFFFFFFFFu - (unsigned)bk;
    }
    if (lane == 0) {
        g_bestn[token] = nstar;
        out[IND_OFF + token] = (float)nstar;
    }
}

// ---------------- kernel 4: gather + outputs + diff partials --------------
__global__ __launch_bounds__(256) void k_gather(const float* __restrict__ x,
                                                float* __restrict__ out) {
    __shared__ unsigned ns[16];
    __shared__ double s_red[8];
    int tid = threadIdx.x, lane = tid & 31, wid = tid >> 5;
    int tok0 = blockIdx.x * 16;
    int b = tok0 >> 11;

    if (tid < 16) ns[tid] = g_bestn[tok0 + tid];
    __syncthreads();

    const float* cbb = g_cb + (size_t)b * Nq * Dq;
    const float4* x4 = (const float4*)(x + (size_t)tok0 * Dq);
    float4* o4 = (float4*)(out + (size_t)tok0 * Dq);

    float s32 = 0.f;
    double s = 0.0;
#pragma unroll
    for (int i = 0; i < 4; i++) {
        int f = tid + i*256;
        int tl = f >> 6;
        int dd = (f & 63);
        float4 q = ((const float4*)(cbb + (size_t)ns[tl]*Dq))[dd];
        float4 xv = x4[f];
        float dx = __fsub_rn(q.x, xv.x), dy = __fsub_rn(q.y, xv.y);
        float dz = __fsub_rn(q.z, xv.z), dw = __fsub_rn(q.w, xv.w);
        float4 r;
        r.x = __fmul_rn(__fadd_rn(q.x, __fadd_rn(xv.x, dx)), 0.5f);
        r.y = __fmul_rn(__fadd_rn(q.y, __fadd_rn(xv.y, dy)), 0.5f);
        r.z = __fmul_rn(__fadd_rn(q.z, __fadd_rn(xv.z, dz)), 0.5f);
        r.w = __fmul_rn(__fadd_rn(q.w, __fadd_rn(xv.w, dw)), 0.5f);
        o4[f] = r;
        s32 = fmaf(dx, dx, s32); s32 = fmaf(dy, dy, s32);
        s32 = fmaf(dz, dz, s32); s32 = fmaf(dw, dw, s32);
        if (i == 1) { s += (double)s32; s32 = 0.f; }
    }
    s += (double)s32;

#pragma unroll
    for (int off = 16; off > 0; off >>= 1) s += __shfl_down_sync(0xffffffffu, s, off);
    if (lane == 0) s_red[wid] = s;
    __syncthreads();
    if (tid == 0) {
        double t = 0.0;
        for (int i = 0; i < 8; i++) t += s_red[i];
        g_diff_partial[blockIdx.x] = t;
    }
}

// ---------------- kernel 5: deterministic final diff reduce ---------------
__global__ __launch_bounds__(256) void k_diff(float* __restrict__ out) {
    __shared__ double sr[256];
    int tid = threadIdx.x;
    double s = 0.0;
    for (int i = tid; i < GATHER_BLOCKS; i += 256) s += g_diff_partial[i];
    sr[tid] = s;
    __syncthreads();
    for (int off = 128; off > 0; off >>= 1) {
        if (tid < off) sr[tid] += sr[tid + off];
        __syncthreads();
    }
    if (tid == 0) out[DIFF_OFF] = (float)(sr[0] / (double)Q_ELEMS);
}

// ---------------- launch ----------------
extern "C" void kernel_launch(void* const* d_in, const int* in_sizes, int n_in,
                              void* d_out, int out_size) {
    const float* inp = (const float*)d_in[0];   // (16,2048,256)
    const float* spk = (const float*)d_in[1];   // (3,16,256)
    const float* emb = (const float*)d_in[2];   // (512,256,256)
    float* out = (float*)d_out;                 // [quantize | diff | embed_ind]

    k_prep<<<Bq*Tq/8, 256>>>(inp);
    k_codebook<<<512, 128>>>(emb, spk);
    k_scores_mma<<<1024, 256>>>();
    k_select<<<Bq*Tq/8, 256>>>(inp, out);
    k_gather<<<GATHER_BLOCKS, 256>>>(inp, out);
    k_diff<<<1, 256>>>(out);
}

// round 12
// speedup vs baseline: 1.8173x; 1.2444x over previous
#include <cuda_runtime.h>
#include <cuda_fp16.h>
#include <cstdint>

#define Bq 16
#define Tq 2048
#define Dq 256
#define Nq 512

#define Q_ELEMS (Bq*Tq*Dq)          /* 8388608 */
#define DIFF_OFF Q_ELEMS
#define IND_OFF  (Q_ELEMS + 1)
#define GATHER_BLOCKS (Bq*Tq/16)    /* 2048 */
#define EPS_SEL 0.15f
#define ASTRIDE 144                  /* smem row stride bytes (128 data + 16 pad) */

// ---------------- scratch (no allocations allowed) ----------------
__device__ float g_cb[Bq*Nq*Dq];                       // e codebook [b][n][d]
__device__ float g_see[Bq*Nq];                         // sum(e^2), XLA-tree order
__device__ float g_sxx[Bq*Tq];                         // sum(x^2), XLA-tree order
__device__ __align__(16) __half g_xh[Bq*Tq*Dq];        // x fp16
__device__ __align__(16) __half g_eh[Bq*Nq*Dq];        // e fp16
__device__ float g_dot[(size_t)Bq*Tq*Nq];              // approx dots, 67 MB
__device__ unsigned g_bestn[Bq*Tq];
__device__ double g_diff_partial[GATHER_BLOCKS];

// ---------------- helpers ----------------
__device__ __forceinline__ unsigned long long make_key(float s, int n) {
    unsigned u = __float_as_uint(s);
    u = (u & 0x80000000u) ? ~u : (u | 0x80000000u);
    return ((unsigned long long)u << 32) | (unsigned long long)(0xFFFFFFFFu - (unsigned)n);
}
__device__ __forceinline__ unsigned long long fma2(unsigned long long a,
                                                   unsigned long long x,
                                                   unsigned long long e) {
    asm("fma.rn.f32x2 %0, %1, %2, %0;" : "+l"(a) : "l"(x), "l"(e));
    return a;
}
__device__ __forceinline__ unsigned long long dup2(float v) {
    unsigned long long r; asm("mov.b64 %0, {%1, %1};" : "=l"(r) : "f"(v)); return r;
}
__device__ __forceinline__ unsigned long long pack2(float lo, float hi) {
    unsigned long long r; asm("mov.b64 %0, {%1, %2};" : "=l"(r) : "f"(lo), "f"(hi)); return r;
}
__device__ __forceinline__ void unpack2(unsigned long long v, float& lo, float& hi) {
    asm("mov.b64 {%0, %1}, %2;" : "=f"(lo), "=f"(hi) : "l"(v));
}
__device__ __forceinline__ float warp_tree_sum(float p) {
#pragma unroll
    for (int off = 16; off > 0; off >>= 1)
        p = __fadd_rn(p, __shfl_down_sync(0xffffffffu, p, off));
    return p;
}
__device__ __forceinline__ uint32_t smem_u32(const void* p) {
    uint32_t a;
    asm("{ .reg .u64 t; cvta.to.shared.u64 t, %1; cvt.u32.u64 %0, t; }" : "=r"(a) : "l"(p));
    return a;
}
__device__ __forceinline__ void ldsm_x4(uint32_t r[4], uint32_t addr) {
    asm volatile("ldmatrix.sync.aligned.m8n8.x4.shared.b16 {%0,%1,%2,%3}, [%4];"
        : "=r"(r[0]), "=r"(r[1]), "=r"(r[2]), "=r"(r[3]) : "r"(addr));
}
__device__ __forceinline__ void mma16816(float c[4], const uint32_t a[4],
                                         uint32_t b0, uint32_t b1) {
    asm volatile("mma.sync.aligned.m16n8k16.row.col.f32.f16.f16.f32 "
        "{%0,%1,%2,%3}, {%4,%5,%6,%7}, {%8,%9}, {%0,%1,%2,%3};"
        : "+f"(c[0]), "+f"(c[1]), "+f"(c[2]), "+f"(c[3])
        : "r"(a[0]), "r"(a[1]), "r"(a[2]), "r"(a[3]), "r"(b0), "r"(b1));
}

// ---------------- kernel 0: sxx (XLA order) + x fp16 --------------
__global__ __launch_bounds__(256) void k_prep(const float* __restrict__ x) {
    int tid = threadIdx.x, lane = tid & 31, wid = tid >> 5;
    int token = blockIdx.x * 8 + wid;
    const float* xt = x + (size_t)token * Dq;
    float p = 0.f;
#pragma unroll
    for (int j = 0; j < 8; j++) {
        float c = xt[lane + 32*j];
        p = __fadd_rn(p, __fmul_rn(c, c));
        g_xh[(size_t)token * Dq + lane + 32*j] = __float2half_rn(c);
    }
    p = warp_tree_sum(p);
    if (lane == 0) g_sxx[token] = p;
}

// ---------------- kernel 1: codebook build (+ e fp16) -------------
__global__ __launch_bounds__(128) void k_codebook(const float* __restrict__ emb,
                                                  const float* __restrict__ spk) {
    __shared__ float As[256*33];
    __shared__ unsigned long long Ms2[8*32];
    __shared__ float normS[16];

    int tid = threadIdx.x;
    int lane = tid & 31, wid = tid >> 5;
    int n = blockIdx.x;
    const float* embn = emb + (size_t)n * (Dq*Dq);
    const float* mul  = spk + 2*Bq*Dq;
    const float* addv = spk + 1*Bq*Dq;

    unsigned long long accp[2][8];
#pragma unroll
    for (int r = 0; r < 2; r++)
#pragma unroll
        for (int p = 0; p < 8; p++) accp[r][p] = 0ull;

    for (int kc = 0; kc < 256; kc += 32) {
        __syncthreads();
        for (int i = tid; i < 256; i += 128) {
            int p = i >> 5, j = i & 31;
            Ms2[i] = pack2(mul[(2*p)*256 + kc + j], mul[(2*p+1)*256 + kc + j]);
        }
        for (int f = tid; f < 2048; f += 128) {
            int d = f >> 3, jg = f & 7;
            float4 v = *(const float4*)(embn + (size_t)d*256 + kc + jg*4);
            int base = d*33 + jg*4;
            As[base+0] = v.x; As[base+1] = v.y; As[base+2] = v.z; As[base+3] = v.w;
        }
        __syncthreads();

        const float* a0 = As + tid*33;
        const float* a1 = As + (tid+128)*33;
#pragma unroll 4
        for (int j = 0; j < 32; j++) {
            unsigned long long xv0 = dup2(a0[j]);
            unsigned long long xv1 = dup2(a1[j]);
#pragma unroll
            for (int p = 0; p < 8; p++) {
                unsigned long long m = Ms2[p*32 + j];
                accp[0][p] = fma2(accp[0][p], xv0, m);
                accp[1][p] = fma2(accp[1][p], xv1, m);
            }
        }
    }

    float acc[2][16];
#pragma unroll
    for (int r = 0; r < 2; r++)
#pragma unroll
        for (int p = 0; p < 8; p++)
            unpack2(accp[r][p], acc[r][2*p], acc[r][2*p+1]);

    __syncthreads();
#pragma unroll
    for (int r = 0; r < 2; r++)
#pragma unroll
        for (int b = 0; b < 16; b++) As[b*258 + tid + r*128] = acc[r][b];
    __syncthreads();

#pragma unroll
    for (int bb = 0; bb < 4; bb++) {
        int b = wid*4 + bb;
        const float* row = As + b*258;
        float p = 0.f;
#pragma unroll
        for (int j = 0; j < 8; j++) {
            float c = row[lane + 32*j];
            p = __fadd_rn(p, __fmul_rn(c, c));
        }
        p = warp_tree_sum(p);
        if (lane == 0) normS[b] = __fsqrt_rn(p);
    }
    __syncthreads();

#pragma unroll
    for (int r = 0; r < 2; r++) {
        int d = tid + r*128;
#pragma unroll
        for (int b = 0; b < 16; b++) {
            float ef = __fadd_rn(__fdiv_rn(acc[r][b], normS[b]), addv[b*256 + d]);
            size_t o = ((size_t)(b*Nq + n))*Dq + d;
            g_cb[o] = ef;
            As[b*258 + d] = ef;
            g_eh[o] = __float2half_rn(ef);
        }
    }
    __syncthreads();

#pragma unroll
    for (int bb = 0; bb < 4; bb++) {
        int b = wid*4 + bb;
        const float* row = As + b*258;
        float p = 0.f;
#pragma unroll
        for (int j = 0; j < 8; j++) {
            float c = row[lane + 32*j];
            p = __fadd_rn(p, __fmul_rn(c, c));
        }
        p = warp_tree_sum(p);
        if (lane == 0) g_see[b*Nq + n] = p;
    }
}

// ---------------- kernel 2: HMMA fp16 dot GEMM ----------------------------
// tile 128t x 128n, 8 warps (2x4), per-warp 64t x 32n via 4x4 m16n8k16.
__global__ __launch_bounds__(256, 2) void k_scores_mma() {
    __shared__ __align__(16) unsigned char sA[128*ASTRIDE];
    __shared__ __align__(16) unsigned char sB[128*ASTRIDE];

    int tid = threadIdx.x, wid = tid >> 5, lane = tid & 31;
    int tile = blockIdx.x;
    int b = tile >> 6, rem = tile & 63;
    int t0 = (rem >> 2) * 128, n0 = (rem & 3) * 128;
    int wy = wid >> 2, wx = wid & 3;

    float acc[4][4][4];
#pragma unroll
    for (int i = 0; i < 4; i++)
#pragma unroll
        for (int j = 0; j < 4; j++)
#pragma unroll
            for (int c = 0; c < 4; c++) acc[i][j][c] = 0.f;

    int lrow = tid >> 1, lhalf = tid & 1;

    uint32_t aBase = smem_u32(sA), bBase = smem_u32(sB);
    uint32_t aAddr0 = aBase + (uint32_t)(wy*64 + (lane & 15)) * ASTRIDE + ((lane >> 4) * 16);
    uint32_t bAddr0 = bBase + (uint32_t)(wx*32 + ((lane >> 4) << 3) + (lane & 7)) * ASTRIDE
                            + (((lane >> 3) & 1) * 16);

    const __half* gX = g_xh + ((size_t)(b*Tq + t0)) * Dq;
    const __half* gE = g_eh + ((size_t)(b*Nq + n0)) * Dq;

    uint4 pa[4], pb[4];
    {
        const uint4* srcA = (const uint4*)(gX + (size_t)lrow*Dq + lhalf*32);
        const uint4* srcB = (const uint4*)(gE + (size_t)lrow*Dq + lhalf*32);
#pragma unroll
        for (int q = 0; q < 4; q++) { pa[q] = srcA[q]; pb[q] = srcB[q]; }
    }

    for (int c = 0; c < 4; c++) {
        __syncthreads();
        {
            uint4* dstA = (uint4*)(sA + lrow*ASTRIDE + lhalf*64);
            uint4* dstB = (uint4*)(sB + lrow*ASTRIDE + lhalf*64);
#pragma unroll
            for (int q = 0; q < 4; q++) { dstA[q] = pa[q]; dstB[q] = pb[q]; }
        }
        __syncthreads();
        if (c < 3) {
            int kc = (c + 1) * 64;
            const uint4* srcA = (const uint4*)(gX + (size_t)lrow*Dq + kc + lhalf*32);
            const uint4* srcB = (const uint4*)(gE + (size_t)lrow*Dq + kc + lhalf*32);
#pragma unroll
            for (int q = 0; q < 4; q++) { pa[q] = srcA[q]; pb[q] = srcB[q]; }
        }
#pragma unroll
        for (int s = 0; s < 4; s++) {
            uint32_t bfr[2][4];
#pragma unroll
            for (int p = 0; p < 2; p++)
                ldsm_x4(bfr[p], bAddr0 + (uint32_t)(p*16)*ASTRIDE + s*32);
#pragma unroll
            for (int mt = 0; mt < 4; mt++) {
                uint32_t afr[4];
                ldsm_x4(afr, aAddr0 + (uint32_t)(mt*16)*ASTRIDE + s*32);
#pragma unroll
                for (int nt = 0; nt < 4; nt++) {
                    int p = nt >> 1, q = nt & 1;
                    mma16816(acc[mt][nt], afr, bfr[p][2*q], bfr[p][2*q + 1]);
                }
            }
        }
    }

    int gid = lane >> 2, tid4 = lane & 3;
#pragma unroll
    for (int mt = 0; mt < 4; mt++) {
        int t = t0 + wy*64 + mt*16 + gid;
        float* d0 = g_dot + ((size_t)(b*Tq) + t) * Nq;
        float* d1 = g_dot + ((size_t)(b*Tq) + t + 8) * Nq;
#pragma unroll
        for (int nt = 0; nt < 4; nt++) {
            int n = n0 + wx*32 + nt*8 + tid4*2;
            *(float2*)(d0 + n) = make_float2(acc[mt][nt][0], acc[mt][nt][1]);
            *(float2*)(d1 + n) = make_float2(acc[mt][nt][2], acc[mt][nt][3]);
        }
    }
}

// ---------------- kernel 3: select — approx min + compacted exact rescore -
__global__ __launch_bounds__(256) void k_select(const float* __restrict__ x,
                                                float* __restrict__ out) {
    __shared__ int candN[8][512];
    __shared__ float sx[8][256];

    int tid = threadIdx.x, lane = tid & 31, wid = tid >> 5;
    int token = blockIdx.x * 8 + wid;
    int b = token >> 11;
    float sxx = g_sxx[token];
    const float* dotp = g_dot + (size_t)token * Nq;
    const float* seep = g_see + b * Nq;

    float dloc[16];
    float dmin = 3.4e38f;
#pragma unroll
    for (int j = 0; j < 16; j++) {
        int n = lane + 32*j;
        float dist = __fadd_rn(__fsub_rn(sxx, __fmul_rn(2.0f, dotp[n])), seep[n]);
        dloc[j] = dist;
        dmin = fminf(dmin, dist);
    }
#pragma unroll
    for (int off = 16; off > 0; off >>= 1)
        dmin = fminf(dmin, __shfl_xor_sync(0xffffffffu, dmin, off));

    float thr = dmin + EPS_SEL;
    unsigned mask16 = 0;
#pragma unroll
    for (int j = 0; j < 16; j++)
        if (dloc[j] <= thr) mask16 |= (1u << j);
    int myCount = __popc(mask16);
    // inclusive warp scan of counts
    int incl = myCount;
#pragma unroll
    for (int off = 1; off < 32; off <<= 1) {
        int o = __shfl_up_sync(0xffffffffu, incl, off);
        if (lane >= off) incl += o;
    }
    int total = __shfl_sync(0xffffffffu, incl, 31);
    int myBase = incl - myCount;

    unsigned nstar;
    if (total == 1) {
        unsigned nm = 0xFFFFFFFFu;
#pragma unroll
        for (int j = 0; j < 16; j++)
            if (dloc[j] <= thr) nm = (unsigned)(lane + 32*j);
#pragma unroll
        for (int off = 16; off > 0; off >>= 1)
            nm = min(nm, __shfl_xor_sync(0xffffffffu, nm, off));
        nstar = nm;
    } else {
        // compact candidates into smem, one chain per lane per 32-chunk
        int c = 0;
#pragma unroll
        for (int j = 0; j < 16; j++)
            if (mask16 & (1u << j)) candN[wid][myBase + c++] = lane + 32*j;
        // stage x row into smem (coalesced)
        const float* xr = x + (size_t)token * Dq;
#pragma unroll
        for (int j = 0; j < 8; j++) sx[wid][lane + 32*j] = xr[lane + 32*j];
        __syncwarp();

        const float* sxr = sx[wid];
        unsigned long long bk = 0ull;
        for (int base = 0; base < total; base += 32) {
            int idx = base + lane;
            unsigned long long key = 0ull;
            if (idx < total) {
                int n = candN[wid][idx];
                const float* er = g_cb + ((size_t)(b*Nq + n))*Dq;
                float acc = 0.f;
                // exact ref chain: sequential fp32 fmaf, k ascending
                for (int k = 0; k < 256; k += 4) {
                    float4 ev = *(const float4*)(er + k);
                    acc = __fmaf_rn(sxr[k+0], ev.x, acc);
                    acc = __fmaf_rn(sxr[k+1], ev.y, acc);
                    acc = __fmaf_rn(sxr[k+2], ev.z, acc);
                    acc = __fmaf_rn(sxr[k+3], ev.w, acc);
                }
                float dist = __fadd_rn(__fsub_rn(sxx, __fmul_rn(2.0f, acc)), seep[n]);
                key = make_key(-dist, n);
            }
            if (key > bk) bk = key;
        }
#pragma unroll
        for (int off = 16; off > 0; off >>= 1) {
            unsigned long long o = __shfl_xor_sync(0xffffffffu, bk, off);
            if (o > bk) bk = o;
        }
        nstar = 0xFFFFFFFFu - (unsigned)bk;
    }
    if (lane == 0) {
        g_bestn[token] = nstar;
        out[IND_OFF + token] = (float)nstar;
    }
}

// ---------------- kernel 4: gather + outputs + diff partials --------------
__global__ __launch_bounds__(256) void k_gather(const float* __restrict__ x,
                                                float* __restrict__ out) {
    __shared__ unsigned ns[16];
    __shared__ double s_red[8];
    int tid = threadIdx.x, lane = tid & 31, wid = tid >> 5;
    int tok0 = blockIdx.x * 16;
    int b = tok0 >> 11;

    if (tid < 16) ns[tid] = g_bestn[tok0 + tid];
    __syncthreads();

    const float* cbb = g_cb + (size_t)b * Nq * Dq;
    const float4* x4 = (const float4*)(x + (size_t)tok0 * Dq);
    float4* o4 = (float4*)(out + (size_t)tok0 * Dq);

    float s32 = 0.f;
    double s = 0.0;
#pragma unroll
    for (int i = 0; i < 4; i++) {
        int f = tid + i*256;
        int tl = f >> 6;
        int dd = (f & 63);
        float4 q = ((const float4*)(cbb + (size_t)ns[tl]*Dq))[dd];
        float4 xv = x4[f];
        float dx = __fsub_rn(q.x, xv.x), dy = __fsub_rn(q.y, xv.y);
        float dz = __fsub_rn(q.z, xv.z), dw = __fsub_rn(q.w, xv.w);
        float4 r;
        r.x = __fmul_rn(__fadd_rn(q.x, __fadd_rn(xv.x, dx)), 0.5f);
        r.y = __fmul_rn(__fadd_rn(q.y, __fadd_rn(xv.y, dy)), 0.5f);
        r.z = __fmul_rn(__fadd_rn(q.z, __fadd_rn(xv.z, dz)), 0.5f);
        r.w = __fmul_rn(__fadd_rn(q.w, __fadd_rn(xv.w, dw)), 0.5f);
        o4[f] = r;
        s32 = fmaf(dx, dx, s32); s32 = fmaf(dy, dy, s32);
        s32 = fmaf(dz, dz, s32); s32 = fmaf(dw, dw, s32);
        if (i == 1) { s += (double)s32; s32 = 0.f; }
    }
    s += (double)s32;

#pragma unroll
    for (int off = 16; off > 0; off >>= 1) s += __shfl_down_sync(0xffffffffu, s, off);
    if (lane == 0) s_red[wid] = s;
    __syncthreads();
    if (tid == 0) {
        double t = 0.0;
        for (int i = 0; i < 8; i++) t += s_red[i];
        g_diff_partial[blockIdx.x] = t;
    }
}

// ---------------- kernel 5: deterministic final diff reduce ---------------
__global__ __launch_bounds__(256) void k_diff(float* __restrict__ out) {
    __shared__ double sr[256];
    int tid = threadIdx.x;
    double s = 0.0;
    for (int i = tid; i < GATHER_BLOCKS; i += 256) s += g_diff_partial[i];
    sr[tid] = s;
    __syncthreads();
    for (int off = 128; off > 0; off >>= 1) {
        if (tid < off) sr[tid] += sr[tid + off];
        __syncthreads();
    }
    if (tid == 0) out[DIFF_OFF] = (float)(sr[0] / (double)Q_ELEMS);
}

// ---------------- launch ----------------
extern "C" void kernel_launch(void* const* d_in, const int* in_sizes, int n_in,
                              void* d_out, int out_size) {
    const float* inp = (const float*)d_in[0];   // (16,2048,256)
    const float* spk = (const float*)d_in[1];   // (3,16,256)
    const float* emb = (const float*)d_in[2];   // (512,256,256)
    float* out = (float*)d_out;                 // [quantize | diff | embed_ind]

    k_prep<<<Bq*Tq/8, 256>>>(inp);
    k_codebook<<<512, 128>>>(emb, spk);
    k_scores_mma<<<1024, 256>>>();
    k_select<<<Bq*Tq/8, 256>>>(inp, out);
    k_gather<<<GATHER_BLOCKS, 256>>>(inp, out);
    k_diff<<<1, 256>>>(out);
}

// round 13
// speedup vs baseline: 1.9859x; 1.0928x over previous
#include <cuda_runtime.h>
#include <cuda_fp16.h>
#include <cstdint>

#define Bq 16
#define Tq 2048
#define Dq 256
#define Nq 512

#define Q_ELEMS (Bq*Tq*Dq)          /* 8388608 */
#define DIFF_OFF Q_ELEMS
#define IND_OFF  (Q_ELEMS + 1)
#define SEL_BLOCKS (Bq*Tq/8)        /* 4096 */
#define EPS_SEL 0.15f
#define ASTRIDE 144                  /* smem row stride bytes (128 data + 16 pad) */

// ---------------- scratch (no allocations allowed) ----------------
__device__ float g_cb[Bq*Nq*Dq];                       // e codebook [b][n][d]
__device__ float g_see[Bq*Nq];                         // sum(e^2), XLA-tree order
__device__ float g_sxx[Bq*Tq];                         // sum(x^2), XLA-tree order
__device__ __align__(16) __half g_xh[Bq*Tq*Dq];        // x fp16
__device__ __align__(16) __half g_eh[Bq*Nq*Dq];        // e fp16
__device__ float g_dot[(size_t)Bq*Tq*Nq];              // approx DISTS, 67 MB
__device__ double g_diff_partial[SEL_BLOCKS];

// ---------------- helpers ----------------
__device__ __forceinline__ unsigned long long make_key(float s, int n) {
    unsigned u = __float_as_uint(s);
    u = (u & 0x80000000u) ? ~u : (u | 0x80000000u);
    return ((unsigned long long)u << 32) | (unsigned long long)(0xFFFFFFFFu - (unsigned)n);
}
__device__ __forceinline__ unsigned long long fma2(unsigned long long a,
                                                   unsigned long long x,
                                                   unsigned long long e) {
    asm("fma.rn.f32x2 %0, %1, %2, %0;" : "+l"(a) : "l"(x), "l"(e));
    return a;
}
__device__ __forceinline__ unsigned long long dup2(float v) {
    unsigned long long r; asm("mov.b64 %0, {%1, %1};" : "=l"(r) : "f"(v)); return r;
}
__device__ __forceinline__ unsigned long long pack2(float lo, float hi) {
    unsigned long long r; asm("mov.b64 %0, {%1, %2};" : "=l"(r) : "f"(lo), "f"(hi)); return r;
}
__device__ __forceinline__ void unpack2(unsigned long long v, float& lo, float& hi) {
    asm("mov.b64 {%0, %1}, %2;" : "=f"(lo), "=f"(hi) : "l"(v));
}
__device__ __forceinline__ float warp_tree_sum(float p) {
#pragma unroll
    for (int off = 16; off > 0; off >>= 1)
        p = __fadd_rn(p, __shfl_down_sync(0xffffffffu, p, off));
    return p;
}
__device__ __forceinline__ uint32_t smem_u32(const void* p) {
    uint32_t a;
    asm("{ .reg .u64 t; cvta.to.shared.u64 t, %1; cvt.u32.u64 %0, t; }" : "=r"(a) : "l"(p));
    return a;
}
__device__ __forceinline__ void ldsm_x4(uint32_t r[4], uint32_t addr) {
    asm volatile("ldmatrix.sync.aligned.m8n8.x4.shared.b16 {%0,%1,%2,%3}, [%4];"
        : "=r"(r[0]), "=r"(r[1]), "=r"(r[2]), "=r"(r[3]) : "r"(addr));
}
__device__ __forceinline__ void mma16816(float c[4], const uint32_t a[4],
                                         uint32_t b0, uint32_t b1) {
    asm volatile("mma.sync.aligned.m16n8k16.row.col.f32.f16.f16.f32 "
        "{%0,%1,%2,%3}, {%4,%5,%6,%7}, {%8,%9}, {%0,%1,%2,%3};"
        : "+f"(c[0]), "+f"(c[1]), "+f"(c[2]), "+f"(c[3])
        : "r"(a[0]), "r"(a[1]), "r"(a[2]), "r"(a[3]), "r"(b0), "r"(b1));
}

// ---------------- kernel 0: sxx (XLA order) + x fp16 --------------
__global__ __launch_bounds__(256) void k_prep(const float* __restrict__ x) {
    int tid = threadIdx.x, lane = tid & 31, wid = tid >> 5;
    int token = blockIdx.x * 8 + wid;
    const float* xt = x + (size_t)token * Dq;
    float p = 0.f;
#pragma unroll
    for (int j = 0; j < 8; j++) {
        float c = xt[lane + 32*j];
        p = __fadd_rn(p, __fmul_rn(c, c));
        g_xh[(size_t)token * Dq + lane + 32*j] = __float2half_rn(c);
    }
    p = warp_tree_sum(p);
    if (lane == 0) g_sxx[token] = p;
}

// ---------------- kernel 1: codebook build (+ e fp16) -------------
__global__ __launch_bounds__(128) void k_codebook(const float* __restrict__ emb,
                                                  const float* __restrict__ spk) {
    __shared__ float As[256*33];
    __shared__ unsigned long long Ms2[8*32];
    __shared__ float normS[16];

    int tid = threadIdx.x;
    int lane = tid & 31, wid = tid >> 5;
    int n = blockIdx.x;
    const float* embn = emb + (size_t)n * (Dq*Dq);
    const float* mul  = spk + 2*Bq*Dq;
    const float* addv = spk + 1*Bq*Dq;

    unsigned long long accp[2][8];
#pragma unroll
    for (int r = 0; r < 2; r++)
#pragma unroll
        for (int p = 0; p < 8; p++) accp[r][p] = 0ull;

    for (int kc = 0; kc < 256; kc += 32) {
        __syncthreads();
        for (int i = tid; i < 256; i += 128) {
            int p = i >> 5, j = i & 31;
            Ms2[i] = pack2(mul[(2*p)*256 + kc + j], mul[(2*p+1)*256 + kc + j]);
        }
        for (int f = tid; f < 2048; f += 128) {
            int d = f >> 3, jg = f & 7;
            float4 v = *(const float4*)(embn + (size_t)d*256 + kc + jg*4);
            int base = d*33 + jg*4;
            As[base+0] = v.x; As[base+1] = v.y; As[base+2] = v.z; As[base+3] = v.w;
        }
        __syncthreads();

        const float* a0 = As + tid*33;
        const float* a1 = As + (tid+128)*33;
#pragma unroll 4
        for (int j = 0; j < 32; j++) {
            unsigned long long xv0 = dup2(a0[j]);
            unsigned long long xv1 = dup2(a1[j]);
#pragma unroll
            for (int p = 0; p < 8; p++) {
                unsigned long long m = Ms2[p*32 + j];
                accp[0][p] = fma2(accp[0][p], xv0, m);
                accp[1][p] = fma2(accp[1][p], xv1, m);
            }
        }
    }

    float acc[2][16];
#pragma unroll
    for (int r = 0; r < 2; r++)
#pragma unroll
        for (int p = 0; p < 8; p++)
            unpack2(accp[r][p], acc[r][2*p], acc[r][2*p+1]);

    __syncthreads();
#pragma unroll
    for (int r = 0; r < 2; r++)
#pragma unroll
        for (int b = 0; b < 16; b++) As[b*258 + tid + r*128] = acc[r][b];
    __syncthreads();

#pragma unroll
    for (int bb = 0; bb < 4; bb++) {
        int b = wid*4 + bb;
        const float* row = As + b*258;
        float p = 0.f;
#pragma unroll
        for (int j = 0; j < 8; j++) {
            float c = row[lane + 32*j];
            p = __fadd_rn(p, __fmul_rn(c, c));
        }
        p = warp_tree_sum(p);
        if (lane == 0) normS[b] = __fsqrt_rn(p);
    }
    __syncthreads();

#pragma unroll
    for (int r = 0; r < 2; r++) {
        int d = tid + r*128;
#pragma unroll
        for (int b = 0; b < 16; b++) {
            float ef = __fadd_rn(__fdiv_rn(acc[r][b], normS[b]), addv[b*256 + d]);
            size_t o = ((size_t)(b*Nq + n))*Dq + d;
            g_cb[o] = ef;
            As[b*258 + d] = ef;
            g_eh[o] = __float2half_rn(ef);
        }
    }
    __syncthreads();

#pragma unroll
    for (int bb = 0; bb < 4; bb++) {
        int b = wid*4 + bb;
        const float* row = As + b*258;
        float p = 0.f;
#pragma unroll
        for (int j = 0; j < 8; j++) {
            float c = row[lane + 32*j];
            p = __fadd_rn(p, __fmul_rn(c, c));
        }
        p = warp_tree_sum(p);
        if (lane == 0) g_see[b*Nq + n] = p;
    }
}

// ---------------- kernel 2: HMMA fp16 dist GEMM (1 wave, n-loop) ----------
// 256 blocks = 16b x 16 t-tiles; each block loops n0 over 4 n-tiles.
// Writes dist = (sxx - 2*dot) + see to g_dot.
__global__ __launch_bounds__(256, 2) void k_scores_mma() {
    __shared__ __align__(16) unsigned char sA[128*ASTRIDE];
    __shared__ __align__(16) unsigned char sB[128*ASTRIDE];

    int tid = threadIdx.x, wid = tid >> 5, lane = tid & 31;
    int b = blockIdx.x >> 4;
    int t0 = (blockIdx.x & 15) * 128;
    int wy = wid >> 2, wx = wid & 3;

    int lrow = tid >> 1, lhalf = tid & 1;

    uint32_t aBase = smem_u32(sA), bBase = smem_u32(sB);
    uint32_t aAddr0 = aBase + (uint32_t)(wy*64 + (lane & 15)) * ASTRIDE + ((lane >> 4) * 16);
    uint32_t bAddr0 = bBase + (uint32_t)(wx*32 + ((lane >> 4) << 3) + (lane & 7)) * ASTRIDE
                            + (((lane >> 3) & 1) * 16);

    const __half* gX = g_xh + ((size_t)(b*Tq + t0)) * Dq;

    // per-warp sxx rows (t and t+8 per mt)
    int gid = lane >> 2, tid4 = lane & 3;
    float sxx0[4], sxx1[4];
#pragma unroll
    for (int mt = 0; mt < 4; mt++) {
        int t = t0 + wy*64 + mt*16 + gid;
        sxx0[mt] = g_sxx[b*Tq + t];
        sxx1[mt] = g_sxx[b*Tq + t + 8];
    }

    for (int n0 = 0; n0 < Nq; n0 += 128) {
        const __half* gE = g_eh + ((size_t)(b*Nq + n0)) * Dq;

        float acc[4][4][4];
#pragma unroll
        for (int i = 0; i < 4; i++)
#pragma unroll
            for (int j = 0; j < 4; j++)
#pragma unroll
                for (int c = 0; c < 4; c++) acc[i][j][c] = 0.f;

        uint4 pa[4], pb[4];
        {
            const uint4* srcA = (const uint4*)(gX + (size_t)lrow*Dq + lhalf*32);
            const uint4* srcB = (const uint4*)(gE + (size_t)lrow*Dq + lhalf*32);
#pragma unroll
            for (int q = 0; q < 4; q++) { pa[q] = srcA[q]; pb[q] = srcB[q]; }
        }

        for (int c = 0; c < 4; c++) {
            __syncthreads();   // prior MMAs (this or prev n-tile) done with smem
            {
                uint4* dstA = (uint4*)(sA + lrow*ASTRIDE + lhalf*64);
                uint4* dstB = (uint4*)(sB + lrow*ASTRIDE + lhalf*64);
#pragma unroll
                for (int q = 0; q < 4; q++) { dstA[q] = pa[q]; dstB[q] = pb[q]; }
            }
            __syncthreads();
            if (c < 3) {
                int kc = (c + 1) * 64;
                const uint4* srcA = (const uint4*)(gX + (size_t)lrow*Dq + kc + lhalf*32);
                const uint4* srcB = (const uint4*)(gE + (size_t)lrow*Dq + kc + lhalf*32);
#pragma unroll
                for (int q = 0; q < 4; q++) { pa[q] = srcA[q]; pb[q] = srcB[q]; }
            }
#pragma unroll
            for (int s = 0; s < 4; s++) {
                uint32_t bfr[2][4];
#pragma unroll
                for (int p = 0; p < 2; p++)
                    ldsm_x4(bfr[p], bAddr0 + (uint32_t)(p*16)*ASTRIDE + s*32);
#pragma unroll
                for (int mt = 0; mt < 4; mt++) {
                    uint32_t afr[4];
                    ldsm_x4(afr, aAddr0 + (uint32_t)(mt*16)*ASTRIDE + s*32);
#pragma unroll
                    for (int nt = 0; nt < 4; nt++) {
                        int p = nt >> 1, q = nt & 1;
                        mma16816(acc[mt][nt], afr, bfr[p][2*q], bfr[p][2*q + 1]);
                    }
                }
            }
        }

        // epilogue: fold see/sxx, store dist
#pragma unroll
        for (int mt = 0; mt < 4; mt++) {
            int t = t0 + wy*64 + mt*16 + gid;
            float* d0 = g_dot + ((size_t)(b*Tq) + t) * Nq;
            float* d1 = g_dot + ((size_t)(b*Tq) + t + 8) * Nq;
#pragma unroll
            for (int nt = 0; nt < 4; nt++) {
                int n = n0 + wx*32 + nt*8 + tid4*2;
                float se0 = g_see[b*Nq + n], se1 = g_see[b*Nq + n + 1];
                float q00 = (sxx0[mt] - 2.0f*acc[mt][nt][0]) + se0;
                float q01 = (sxx0[mt] - 2.0f*acc[mt][nt][1]) + se1;
                float q10 = (sxx1[mt] - 2.0f*acc[mt][nt][2]) + se0;
                float q11 = (sxx1[mt] - 2.0f*acc[mt][nt][3]) + se1;
                *(float2*)(d0 + n) = make_float2(q00, q01);
                *(float2*)(d1 + n) = make_float2(q10, q11);
            }
        }
    }
}

// ---------------- kernel 3: select + gather fused --------------------------
__global__ __launch_bounds__(256) void k_select(const float* __restrict__ x,
                                                float* __restrict__ out) {
    __shared__ int candN[8][128];
    __shared__ float sx[8][256];
    __shared__ double s_red[8];

    int tid = threadIdx.x, lane = tid & 31, wid = tid >> 5;
    int token = blockIdx.x * 8 + wid;
    int b = token >> 11;
    const float4* dist4 = (const float4*)(g_dot + (size_t)token * Nq);

    float dloc[16];
    float dmin = 3.4e38f;
#pragma unroll
    for (int j = 0; j < 4; j++) {
        float4 dv = dist4[lane + 32*j];
        dloc[4*j+0] = dv.x; dloc[4*j+1] = dv.y;
        dloc[4*j+2] = dv.z; dloc[4*j+3] = dv.w;
        dmin = fminf(dmin, fminf(fminf(dv.x, dv.y), fminf(dv.z, dv.w)));
    }
#pragma unroll
    for (int off = 16; off > 0; off >>= 1)
        dmin = fminf(dmin, __shfl_xor_sync(0xffffffffu, dmin, off));

    float thr = dmin + EPS_SEL;
    unsigned mask16 = 0;
#pragma unroll
    for (int j = 0; j < 16; j++)
        if (dloc[j] <= thr) mask16 |= (1u << j);
    int myCount = __popc(mask16);
    int incl = myCount;
#pragma unroll
    for (int off = 1; off < 32; off <<= 1) {
        int o = __shfl_up_sync(0xffffffffu, incl, off);
        if (lane >= off) incl += o;
    }
    int total = __shfl_sync(0xffffffffu, incl, 31);
    int myBase = incl - myCount;

    unsigned nstar;
    if (total == 1) {
        unsigned nm = 0xFFFFFFFFu;
#pragma unroll
        for (int j = 0; j < 16; j++)
            if (dloc[j] <= thr) nm = (unsigned)(4*(lane + 32*(j >> 2)) + (j & 3));
#pragma unroll
        for (int off = 16; off > 0; off >>= 1)
            nm = min(nm, __shfl_xor_sync(0xffffffffu, nm, off));
        nstar = nm;
    } else {
        float sxx = g_sxx[token];
        const float* seep = g_see + b * Nq;
        const float* xr = x + (size_t)token * Dq;
#pragma unroll
        for (int j = 0; j < 8; j++) sx[wid][lane + 32*j] = xr[lane + 32*j];
        __syncwarp();
        const float* sxr = sx[wid];
        unsigned long long bk = 0ull;

        if (total <= 128) {
            int c = 0;
#pragma unroll
            for (int j = 0; j < 16; j++)
                if (mask16 & (1u << j))
                    candN[wid][myBase + c++] = 4*(lane + 32*(j >> 2)) + (j & 3);
            __syncwarp();
            for (int base = 0; base < total; base += 32) {
                int idx = base + lane;
                unsigned long long key = 0ull;
                if (idx < total) {
                    int n = candN[wid][idx];
                    const float* er = g_cb + ((size_t)(b*Nq + n))*Dq;
                    float acc = 0.f;
                    for (int k = 0; k < 256; k += 4) {
                        float4 ev = *(const float4*)(er + k);
                        acc = __fmaf_rn(sxr[k+0], ev.x, acc);
                        acc = __fmaf_rn(sxr[k+1], ev.y, acc);
                        acc = __fmaf_rn(sxr[k+2], ev.z, acc);
                        acc = __fmaf_rn(sxr[k+3], ev.w, acc);
                    }
                    float dist = __fadd_rn(__fsub_rn(sxx, __fmul_rn(2.0f, acc)), seep[n]);
                    key = make_key(-dist, n);
                }
                if (key > bk) bk = key;
            }
        } else {
            // overflow fallback (never expected): divergent per-j rescore
            for (int j = 0; j < 16; j++) {
                if (mask16 & (1u << j)) {
                    int n = 4*(lane + 32*(j >> 2)) + (j & 3);
                    const float* er = g_cb + ((size_t)(b*Nq + n))*Dq;
                    float acc = 0.f;
                    for (int k = 0; k < 256; k++)
                        acc = __fmaf_rn(sxr[k], er[k], acc);
                    float dist = __fadd_rn(__fsub_rn(sxx, __fmul_rn(2.0f, acc)), seep[n]);
                    unsigned long long key = make_key(-dist, n);
                    if (key > bk) bk = key;
                }
            }
        }
#pragma unroll
        for (int off = 16; off > 0; off >>= 1) {
            unsigned long long o = __shfl_xor_sync(0xffffffffu, bk, off);
            if (o > bk) bk = o;
        }
        nstar = 0xFFFFFFFFu - (unsigned)bk;
    }
    if (lane == 0) out[IND_OFF + token] = (float)nstar;

    // ---- fused gather + quantize + diff ----
    const float4* q4 = (const float4*)(g_cb + ((size_t)(b*Nq) + nstar) * Dq);
    const float4* x4 = (const float4*)(x + (size_t)token * Dq);
    float4* o4 = (float4*)(out + (size_t)token * Dq);

    float s32 = 0.f;
    double s = 0.0;
#pragma unroll
    for (int p = 0; p < 2; p++) {
        int f = lane + p*32;
        float4 q = q4[f], xv = x4[f];
        float dx = __fsub_rn(q.x, xv.x), dy = __fsub_rn(q.y, xv.y);
        float dz = __fsub_rn(q.z, xv.z), dw = __fsub_rn(q.w, xv.w);
        float4 r;
        r.x = __fmul_rn(__fadd_rn(q.x, __fadd_rn(xv.x, dx)), 0.5f);
        r.y = __fmul_rn(__fadd_rn(q.y, __fadd_rn(xv.y, dy)), 0.5f);
        r.z = __fmul_rn(__fadd_rn(q.z, __fadd_rn(xv.z, dz)), 0.5f);
        r.w = __fmul_rn(__fadd_rn(q.w, __fadd_rn(xv.w, dw)), 0.5f);
        o4[f] = r;
        s32 = fmaf(dx, dx, s32); s32 = fmaf(dy, dy, s32);
        s32 = fmaf(dz, dz, s32); s32 = fmaf(dw, dw, s32);
        if (p == 0) { s += (double)s32; s32 = 0.f; }
    }
    s += (double)s32;

#pragma unroll
    for (int off = 16; off > 0; off >>= 1) s += __shfl_down_sync(0xffffffffu, s, off);
    if (lane == 0) s_red[wid] = s;
    __syncthreads();
    if (tid == 0) {
        double t = 0.0;
        for (int i = 0; i < 8; i++) t += s_red[i];
        g_diff_partial[blockIdx.x] = t;
    }
}

// ---------------- kernel 4: deterministic final diff reduce ---------------
__global__ __launch_bounds__(256) void k_diff(float* __restrict__ out) {
    __shared__ double sr[256];
    int tid = threadIdx.x;
    double s = 0.0;
    for (int i = tid; i < SEL_BLOCKS; i += 256) s += g_diff_partial[i];
    sr[tid] = s;
    __syncthreads();
    for (int off = 128; off > 0; off >>= 1) {
        if (tid < off) sr[tid] += sr[tid + off];
        __syncthreads();
    }
    if (tid == 0) out[DIFF_OFF] = (float)(sr[0] / (double)Q_ELEMS);
}

// ---------------- launch ----------------
extern "C" void kernel_launch(void* const* d_in, const int* in_sizes, int n_in,
                              void* d_out, int out_size) {
    const float* inp = (const float*)d_in[0];   // (16,2048,256)
    const float* spk = (const float*)d_in[1];   // (3,16,256)
    const float* emb = (const float*)d_in[2];   // (512,256,256)
    float* out = (float*)d_out;                 // [quantize | diff | embed_ind]

    k_prep<<<Bq*Tq/8, 256>>>(inp);
    k_codebook<<<512, 128>>>(emb, spk);
    k_scores_mma<<<256, 256>>>();
    k_select<<<SEL_BLOCKS, 256>>>(inp, out);
    k_diff<<<1, 256>>>(out);
}

// round 14
// speedup vs baseline: 2.0889x; 1.0519x over previous
#include <cuda_runtime.h>
#include <cuda_fp16.h>
#include <cstdint>

#define Bq 16
#define Tq 2048
#define Dq 256
#define Nq 512

#define Q_ELEMS (Bq*Tq*Dq)          /* 8388608 */
#define DIFF_OFF Q_ELEMS
#define IND_OFF  (Q_ELEMS + 1)
#define SEL_BLOCKS (Bq*Tq/8)        /* 4096 */
#define EPS_SEL 0.15f
#define ASTRIDE 144                  /* smem row stride bytes (128 data + 16 pad) */

// ---------------- scratch (no allocations allowed) ----------------
__device__ float g_cb[Bq*Nq*Dq];                       // e codebook [b][n][d]
__device__ float g_see[Bq*Nq];                         // sum(e^2), XLA-tree order
__device__ float g_sxx[Bq*Tq];                         // sum(x^2), XLA-tree order
__device__ __align__(16) __half g_xh[Bq*Tq*Dq];        // x fp16
__device__ __align__(16) __half g_eh[Bq*Nq*Dq];        // e fp16
__device__ float g_dot[(size_t)Bq*Tq*Nq];              // approx DISTS, 67 MB
__device__ double g_diff_partial[SEL_BLOCKS];

// ---------------- helpers ----------------
__device__ __forceinline__ unsigned long long make_key(float s, int n) {
    unsigned u = __float_as_uint(s);
    u = (u & 0x80000000u) ? ~u : (u | 0x80000000u);
    return ((unsigned long long)u << 32) | (unsigned long long)(0xFFFFFFFFu - (unsigned)n);
}
__device__ __forceinline__ unsigned long long fma2(unsigned long long a,
                                                   unsigned long long x,
                                                   unsigned long long e) {
    asm("fma.rn.f32x2 %0, %1, %2, %0;" : "+l"(a) : "l"(x), "l"(e));
    return a;
}
__device__ __forceinline__ unsigned long long dup2(float v) {
    unsigned long long r; asm("mov.b64 %0, {%1, %1};" : "=l"(r) : "f"(v)); return r;
}
__device__ __forceinline__ unsigned long long pack2(float lo, float hi) {
    unsigned long long r; asm("mov.b64 %0, {%1, %2};" : "=l"(r) : "f"(lo), "f"(hi)); return r;
}
__device__ __forceinline__ void unpack2(unsigned long long v, float& lo, float& hi) {
    asm("mov.b64 {%0, %1}, %2;" : "=f"(lo), "=f"(hi) : "l"(v));
}
__device__ __forceinline__ float warp_tree_sum(float p) {
#pragma unroll
    for (int off = 16; off > 0; off >>= 1)
        p = __fadd_rn(p, __shfl_down_sync(0xffffffffu, p, off));
    return p;
}
__device__ __forceinline__ uint32_t smem_u32(const void* p) {
    uint32_t a;
    asm("{ .reg .u64 t; cvta.to.shared.u64 t, %1; cvt.u32.u64 %0, t; }" : "=r"(a) : "l"(p));
    return a;
}
__device__ __forceinline__ void ldsm_x4(uint32_t r[4], uint32_t addr) {
    asm volatile("ldmatrix.sync.aligned.m8n8.x4.shared.b16 {%0,%1,%2,%3}, [%4];"
        : "=r"(r[0]), "=r"(r[1]), "=r"(r[2]), "=r"(r[3]) : "r"(addr));
}
__device__ __forceinline__ void mma16816(float c[4], const uint32_t a[4],
                                         uint32_t b0, uint32_t b1) {
    asm volatile("mma.sync.aligned.m16n8k16.row.col.f32.f16.f16.f32 "
        "{%0,%1,%2,%3}, {%4,%5,%6,%7}, {%8,%9}, {%0,%1,%2,%3};"
        : "+f"(c[0]), "+f"(c[1]), "+f"(c[2]), "+f"(c[3])
        : "r"(a[0]), "r"(a[1]), "r"(a[2]), "r"(a[3]), "r"(b0), "r"(b1));
}

// ---------------- kernel 0: sxx (XLA order) + x fp16 --------------
__global__ __launch_bounds__(256) void k_prep(const float* __restrict__ x) {
    int tid = threadIdx.x, lane = tid & 31, wid = tid >> 5;
    int token = blockIdx.x * 8 + wid;
    const float* xt = x + (size_t)token * Dq;
    float p = 0.f;
#pragma unroll
    for (int j = 0; j < 8; j++) {
        float c = xt[lane + 32*j];
        p = __fadd_rn(p, __fmul_rn(c, c));
        g_xh[(size_t)token * Dq + lane + 32*j] = __float2half_rn(c);
    }
    p = warp_tree_sum(p);
    if (lane == 0) g_sxx[token] = p;
}

// ---------------- kernel 1: codebook build, double-buffered -------
// chunk = 16 k; register-prefetch of next chunk hides DRAM latency.
// k-ascending FMA chain order identical to prior rounds (bit-exact).
#define CBS 17
__global__ __launch_bounds__(128) void k_codebook(const float* __restrict__ emb,
                                                  const float* __restrict__ spk) {
    __shared__ float As[2][256*CBS];
    __shared__ unsigned long long Ms2[2][128];
    __shared__ float normS[16];

    int tid = threadIdx.x;
    int lane = tid & 31, wid = tid >> 5;
    int n = blockIdx.x;
    const float* embn = emb + (size_t)n * (Dq*Dq);
    const float* mul  = spk + 2*Bq*Dq;
    const float* addv = spk + 1*Bq*Dq;

    unsigned long long accp[2][8];
#pragma unroll
    for (int r = 0; r < 2; r++)
#pragma unroll
        for (int p = 0; p < 8; p++) accp[r][p] = 0ull;

    int mp = tid >> 4, mj = tid & 15;
    float4 pa[8];
    unsigned long long mpre;
    {
        // prefetch chunk 0
#pragma unroll
        for (int i = 0; i < 8; i++) {
            int idx = tid + i*128;
            int d = idx >> 2, jg = idx & 3;
            pa[i] = *(const float4*)(embn + (size_t)d*256 + jg*4);
        }
        mpre = pack2(mul[(2*mp)*256 + mj], mul[(2*mp+1)*256 + mj]);
    }

    for (int c = 0; c < 16; c++) {
        int buf = c & 1;
        __syncthreads();   // buf free: compute c-2 done everywhere
#pragma unroll
        for (int i = 0; i < 8; i++) {
            int idx = tid + i*128;
            int d = idx >> 2, jg = idx & 3;
            int base = d*CBS + jg*4;
            As[buf][base+0] = pa[i].x; As[buf][base+1] = pa[i].y;
            As[buf][base+2] = pa[i].z; As[buf][base+3] = pa[i].w;
        }
        Ms2[buf][tid] = mpre;
        __syncthreads();
        if (c < 15) {
            int kc = (c + 1) * 16;
#pragma unroll
            for (int i = 0; i < 8; i++) {
                int idx = tid + i*128;
                int d = idx >> 2, jg = idx & 3;
                pa[i] = *(const float4*)(embn + (size_t)d*256 + kc + jg*4);
            }
            mpre = pack2(mul[(2*mp)*256 + kc + mj], mul[(2*mp+1)*256 + kc + mj]);
        }
        const float* a0 = As[buf] + tid*CBS;
        const float* a1 = As[buf] + (tid+128)*CBS;
#pragma unroll
        for (int j = 0; j < 16; j++) {
            unsigned long long xv0 = dup2(a0[j]);
            unsigned long long xv1 = dup2(a1[j]);
#pragma unroll
            for (int p = 0; p < 8; p++) {
                unsigned long long m = Ms2[buf][p*16 + j];
                accp[0][p] = fma2(accp[0][p], xv0, m);
                accp[1][p] = fma2(accp[1][p], xv1, m);
            }
        }
    }

    float acc[2][16];
#pragma unroll
    for (int r = 0; r < 2; r++)
#pragma unroll
        for (int p = 0; p < 8; p++)
            unpack2(accp[r][p], acc[r][2*p], acc[r][2*p+1]);

    float* Ep = (float*)As;   // reuse staging as [16][258]
    __syncthreads();
#pragma unroll
    for (int r = 0; r < 2; r++)
#pragma unroll
        for (int b = 0; b < 16; b++) Ep[b*258 + tid + r*128] = acc[r][b];
    __syncthreads();

#pragma unroll
    for (int bb = 0; bb < 4; bb++) {
        int b = wid*4 + bb;
        const float* row = Ep + b*258;
        float p = 0.f;
#pragma unroll
        for (int j = 0; j < 8; j++) {
            float c = row[lane + 32*j];
            p = __fadd_rn(p, __fmul_rn(c, c));
        }
        p = warp_tree_sum(p);
        if (lane == 0) normS[b] = __fsqrt_rn(p);
    }
    __syncthreads();

#pragma unroll
    for (int r = 0; r < 2; r++) {
        int d = tid + r*128;
#pragma unroll
        for (int b = 0; b < 16; b++) {
            float ef = __fadd_rn(__fdiv_rn(acc[r][b], normS[b]), addv[b*256 + d]);
            size_t o = ((size_t)(b*Nq + n))*Dq + d;
            g_cb[o] = ef;
            Ep[b*258 + d] = ef;
            g_eh[o] = __float2half_rn(ef);
        }
    }
    __syncthreads();

#pragma unroll
    for (int bb = 0; bb < 4; bb++) {
        int b = wid*4 + bb;
        const float* row = Ep + b*258;
        float p = 0.f;
#pragma unroll
        for (int j = 0; j < 8; j++) {
            float c = row[lane + 32*j];
            p = __fadd_rn(p, __fmul_rn(c, c));
        }
        p = warp_tree_sum(p);
        if (lane == 0) g_see[b*Nq + n] = p;
    }
}

// ---------------- kernel 2: HMMA fp16 dist GEMM (1024 blocks) -------------
// tile 128t x 128n; writes dist = (sxx - 2*dot) + see to g_dot.
__global__ __launch_bounds__(256, 2) void k_scores_mma() {
    __shared__ __align__(16) unsigned char sA[128*ASTRIDE];
    __shared__ __align__(16) unsigned char sB[128*ASTRIDE];

    int tid = threadIdx.x, wid = tid >> 5, lane = tid & 31;
    int tile = blockIdx.x;
    int b = tile >> 6, rem = tile & 63;
    int t0 = (rem >> 2) * 128, n0 = (rem & 3) * 128;
    int wy = wid >> 2, wx = wid & 3;

    float acc[4][4][4];
#pragma unroll
    for (int i = 0; i < 4; i++)
#pragma unroll
        for (int j = 0; j < 4; j++)
#pragma unroll
            for (int c = 0; c < 4; c++) acc[i][j][c] = 0.f;

    int lrow = tid >> 1, lhalf = tid & 1;

    uint32_t aBase = smem_u32(sA), bBase = smem_u32(sB);
    uint32_t aAddr0 = aBase + (uint32_t)(wy*64 + (lane & 15)) * ASTRIDE + ((lane >> 4) * 16);
    uint32_t bAddr0 = bBase + (uint32_t)(wx*32 + ((lane >> 4) << 3) + (lane & 7)) * ASTRIDE
                            + (((lane >> 3) & 1) * 16);

    const __half* gX = g_xh + ((size_t)(b*Tq + t0)) * Dq;
    const __half* gE = g_eh + ((size_t)(b*Nq + n0)) * Dq;

    uint4 pa[4], pb[4];
    {
        const uint4* srcA = (const uint4*)(gX + (size_t)lrow*Dq + lhalf*32);
        const uint4* srcB = (const uint4*)(gE + (size_t)lrow*Dq + lhalf*32);
#pragma unroll
        for (int q = 0; q < 4; q++) { pa[q] = srcA[q]; pb[q] = srcB[q]; }
    }

    for (int c = 0; c < 4; c++) {
        __syncthreads();
        {
            uint4* dstA = (uint4*)(sA + lrow*ASTRIDE + lhalf*64);
            uint4* dstB = (uint4*)(sB + lrow*ASTRIDE + lhalf*64);
#pragma unroll
            for (int q = 0; q < 4; q++) { dstA[q] = pa[q]; dstB[q] = pb[q]; }
        }
        __syncthreads();
        if (c < 3) {
            int kc = (c + 1) * 64;
            const uint4* srcA = (const uint4*)(gX + (size_t)lrow*Dq + kc + lhalf*32);
            const uint4* srcB = (const uint4*)(gE + (size_t)lrow*Dq + kc + lhalf*32);
#pragma unroll
            for (int q = 0; q < 4; q++) { pa[q] = srcA[q]; pb[q] = srcB[q]; }
        }
#pragma unroll
        for (int s = 0; s < 4; s++) {
            uint32_t bfr[2][4];
#pragma unroll
            for (int p = 0; p < 2; p++)
                ldsm_x4(bfr[p], bAddr0 + (uint32_t)(p*16)*ASTRIDE + s*32);
#pragma unroll
            for (int mt = 0; mt < 4; mt++) {
                uint32_t afr[4];
                ldsm_x4(afr, aAddr0 + (uint32_t)(mt*16)*ASTRIDE + s*32);
#pragma unroll
                for (int nt = 0; nt < 4; nt++) {
                    int p = nt >> 1, q = nt & 1;
                    mma16816(acc[mt][nt], afr, bfr[p][2*q], bfr[p][2*q + 1]);
                }
            }
        }
    }

    // epilogue: fold see/sxx, store dist
    int gid = lane >> 2, tid4 = lane & 3;
#pragma unroll
    for (int mt = 0; mt < 4; mt++) {
        int t = t0 + wy*64 + mt*16 + gid;
        float sx0 = g_sxx[b*Tq + t], sx1 = g_sxx[b*Tq + t + 8];
        float* d0 = g_dot + ((size_t)(b*Tq) + t) * Nq;
        float* d1 = g_dot + ((size_t)(b*Tq) + t + 8) * Nq;
#pragma unroll
        for (int nt = 0; nt < 4; nt++) {
            int n = n0 + wx*32 + nt*8 + tid4*2;
            float2 se = *(const float2*)(g_see + b*Nq + n);
            *(float2*)(d0 + n) = make_float2((sx0 - 2.0f*acc[mt][nt][0]) + se.x,
                                             (sx0 - 2.0f*acc[mt][nt][1]) + se.y);
            *(float2*)(d1 + n) = make_float2((sx1 - 2.0f*acc[mt][nt][2]) + se.x,
                                             (sx1 - 2.0f*acc[mt][nt][3]) + se.y);
        }
    }
}

// ---------------- kernel 3: select + gather fused --------------------------
__global__ __launch_bounds__(256) void k_select(const float* __restrict__ x,
                                                float* __restrict__ out) {
    __shared__ int candN[8][128];
    __shared__ float sx[8][256];
    __shared__ double s_red[8];

    int tid = threadIdx.x, lane = tid & 31, wid = tid >> 5;
    int token = blockIdx.x * 8 + wid;
    int b = token >> 11;
    const float4* dist4 = (const float4*)(g_dot + (size_t)token * Nq);

    float dloc[16];
    float dmin = 3.4e38f;
#pragma unroll
    for (int j = 0; j < 4; j++) {
        float4 dv = dist4[lane + 32*j];
        dloc[4*j+0] = dv.x; dloc[4*j+1] = dv.y;
        dloc[4*j+2] = dv.z; dloc[4*j+3] = dv.w;
        dmin = fminf(dmin, fminf(fminf(dv.x, dv.y), fminf(dv.z, dv.w)));
    }
#pragma unroll
    for (int off = 16; off > 0; off >>= 1)
        dmin = fminf(dmin, __shfl_xor_sync(0xffffffffu, dmin, off));

    float thr = dmin + EPS_SEL;
    unsigned mask16 = 0;
#pragma unroll
    for (int j = 0; j < 16; j++)
        if (dloc[j] <= thr) mask16 |= (1u << j);
    int myCount = __popc(mask16);
    int incl = myCount;
#pragma unroll
    for (int off = 1; off < 32; off <<= 1) {
        int o = __shfl_up_sync(0xffffffffu, incl, off);
        if (lane >= off) incl += o;
    }
    int total = __shfl_sync(0xffffffffu, incl, 31);
    int myBase = incl - myCount;

    unsigned nstar;
    if (total == 1) {
        unsigned nm = 0xFFFFFFFFu;
#pragma unroll
        for (int j = 0; j < 16; j++)
            if (dloc[j] <= thr) nm = (unsigned)(4*(lane + 32*(j >> 2)) + (j & 3));
#pragma unroll
        for (int off = 16; off > 0; off >>= 1)
            nm = min(nm, __shfl_xor_sync(0xffffffffu, nm, off));
        nstar = nm;
    } else {
        float sxx = g_sxx[token];
        const float* seep = g_see + b * Nq;
        const float* xr = x + (size_t)token * Dq;
#pragma unroll
        for (int j = 0; j < 8; j++) sx[wid][lane + 32*j] = xr[lane + 32*j];
        __syncwarp();
        const float* sxr = sx[wid];
        unsigned long long bk = 0ull;

        if (total <= 128) {
            int c = 0;
#pragma unroll
            for (int j = 0; j < 16; j++)
                if (mask16 & (1u << j))
                    candN[wid][myBase + c++] = 4*(lane + 32*(j >> 2)) + (j & 3);
            __syncwarp();
            for (int base = 0; base < total; base += 32) {
                int idx = base + lane;
                unsigned long long key = 0ull;
                if (idx < total) {
                    int n = candN[wid][idx];
                    const float* er = g_cb + ((size_t)(b*Nq + n))*Dq;
                    float acc = 0.f;
                    for (int k = 0; k < 256; k += 4) {
                        float4 ev = *(const float4*)(er + k);
                        acc = __fmaf_rn(sxr[k+0], ev.x, acc);
                        acc = __fmaf_rn(sxr[k+1], ev.y, acc);
                        acc = __fmaf_rn(sxr[k+2], ev.z, acc);
                        acc = __fmaf_rn(sxr[k+3], ev.w, acc);
                    }
                    float dist = __fadd_rn(__fsub_rn(sxx, __fmul_rn(2.0f, acc)), seep[n]);
                    key = make_key(-dist, n);
                }
                if (key > bk) bk = key;
            }
        } else {
            for (int j = 0; j < 16; j++) {
                if (mask16 & (1u << j)) {
                    int n = 4*(lane + 32*(j >> 2)) + (j & 3);
                    const float* er = g_cb + ((size_t)(b*Nq + n))*Dq;
                    float acc = 0.f;
                    for (int k = 0; k < 256; k++)
                        acc = __fmaf_rn(sxr[k], er[k], acc);
                    float dist = __fadd_rn(__fsub_rn(sxx, __fmul_rn(2.0f, acc)), seep[n]);
                    unsigned long long key = make_key(-dist, n);
                    if (key > bk) bk = key;
                }
            }
        }
#pragma unroll
        for (int off = 16; off > 0; off >>= 1) {
            unsigned long long o = __shfl_xor_sync(0xffffffffu, bk, off);
            if (o > bk) bk = o;
        }
        nstar = 0xFFFFFFFFu - (unsigned)bk;
    }
    if (lane == 0) out[IND_OFF + token] = (float)nstar;

    // ---- fused gather + quantize + diff ----
    const float4* q4 = (const float4*)(g_cb + ((size_t)(b*Nq) + nstar) * Dq);
    const float4* x4 = (const float4*)(x + (size_t)token * Dq);
    float4* o4 = (float4*)(out + (size_t)token * Dq);

    float s32 = 0.f;
    double s = 0.0;
#pragma unroll
    for (int p = 0; p < 2; p++) {
        int f = lane + p*32;
        float4 q = q4[f], xv = x4[f];
        float dx = __fsub_rn(q.x, xv.x), dy = __fsub_rn(q.y, xv.y);
        float dz = __fsub_rn(q.z, xv.z), dw = __fsub_rn(q.w, xv.w);
        float4 r;
        r.x = __fmul_rn(__fadd_rn(q.x, __fadd_rn(xv.x, dx)), 0.5f);
        r.y = __fmul_rn(__fadd_rn(q.y, __fadd_rn(xv.y, dy)), 0.5f);
        r.z = __fmul_rn(__fadd_rn(q.z, __fadd_rn(xv.z, dz)), 0.5f);
        r.w = __fmul_rn(__fadd_rn(q.w, __fadd_rn(xv.w, dw)), 0.5f);
        o4[f] = r;
        s32 = fmaf(dx, dx, s32); s32 = fmaf(dy, dy, s32);
        s32 = fmaf(dz, dz, s32); s32 = fmaf(dw, dw, s32);
        if (p == 0) { s += (double)s32; s32 = 0.f; }
    }
    s += (double)s32;

#pragma unroll
    for (int off = 16; off > 0; off >>= 1) s += __shfl_down_sync(0xffffffffu, s, off);
    if (lane == 0) s_red[wid] = s;
    __syncthreads();
    if (tid == 0) {
        double t = 0.0;
        for (int i = 0; i < 8; i++) t += s_red[i];
        g_diff_partial[blockIdx.x] = t;
    }
}

// ---------------- kernel 4: deterministic final diff reduce ---------------
__global__ __launch_bounds__(256) void k_diff(float* __restrict__ out) {
    __shared__ double sr[256];
    int tid = threadIdx.x;
    double s = 0.0;
    for (int i = tid; i < SEL_BLOCKS; i += 256) s += g_diff_partial[i];
    sr[tid] = s;
    __syncthreads();
    for (int off = 128; off > 0; off >>= 1) {
        if (tid < off) sr[tid] += sr[tid + off];
        __syncthreads();
    }
    if (tid == 0) out[DIFF_OFF] = (float)(sr[0] / (double)Q_ELEMS);
}

// ---------------- launch ----------------
extern "C" void kernel_launch(void* const* d_in, const int* in_sizes, int n_in,
                              void* d_out, int out_size) {
    const float* inp = (const float*)d_in[0];   // (16,2048,256)
    const float* spk = (const float*)d_in[1];   // (3,16,256)
    const float* emb = (const float*)d_in[2];   // (512,256,256)
    float* out = (float*)d_out;                 // [quantize | diff | embed_ind]

    k_prep<<<Bq*Tq/8, 256>>>(inp);
    k_codebook<<<512, 128>>>(emb, spk);
    k_scores_mma<<<1024, 256>>>();
    k_select<<<SEL_BLOCKS, 256>>>(inp, out);
    k_diff<<<1, 256>>>(out);
}